// round 9
// baseline (speedup 1.0000x reference)
#include <cuda_runtime.h>
#include <cuda_fp16.h>
#include <cstdint>

#define NN 20000
#define EE 320000
#define TE (EE + NN)          // edges + self loops
#define FIN 128
#define HID 64
#define HEADS 8
#define C1 (HEADS * HID)      // 512
#define NBLK ((NN + 255) / 256)   // 79 scan blocks
#define XB (NN * FIN / 4 / 256)   // 2500 split_x blocks
#define WB (FIN * C1 / 256)       // 256 split_w blocks

// ---------------- scratch (static device globals; no allocation) -------------
__device__ int    g_is64;
__device__ int    g_cnt[NN];
__device__ int    g_off[NN + 1];
__device__ int    g_cur[NN];
__device__ int    g_csr[TE];
__device__ int    g_bsum[NBLK];
__device__ __half g_h1[(size_t)NN * C1];      // 20 MB, fp16 features
__device__ __half g_xhp[(size_t)NN * FIN];    // fp16 hi plane of x   [N][128]
__device__ __half g_xlp[(size_t)NN * FIN];    // fp16 lo plane of x
__device__ __half g_wth[C1 * FIN];            // W1^T hi plane        [n][k]
__device__ __half g_wtl[C1 * FIN];            // W1^T lo plane
__device__ float  g_as1[NN * HEADS];
__device__ float  g_ad1[NN * HEADS];
__device__ float  g_h2[NN * 2];
__device__ float  g_as2[NN];
__device__ float  g_ad2[NN];

// ---------------- fused prep: split_x + split_w + detect + zero cnt ----------
__global__ void k_prep(const float* __restrict__ x, const float* __restrict__ W1,
                       const int* __restrict__ ei) {
    int b = blockIdx.x, t = threadIdx.x;
    if (b < XB) {
        int i = b * 256 + t;
        if (i < NN) g_cnt[i] = 0;
        float4 v = ((const float4*)x)[i];
        __half hx = __float2half_rn(v.x), hy = __float2half_rn(v.y);
        __half hz = __float2half_rn(v.z), hw = __float2half_rn(v.w);
        ((__half2*)g_xhp)[2 * i + 0] = __halves2half2(hx, hy);
        ((__half2*)g_xhp)[2 * i + 1] = __halves2half2(hz, hw);
        ((__half2*)g_xlp)[2 * i + 0] = __halves2half2(
            __float2half_rn(v.x - __half2float(hx)),
            __float2half_rn(v.y - __half2float(hy)));
        ((__half2*)g_xlp)[2 * i + 1] = __halves2half2(
            __float2half_rn(v.z - __half2float(hz)),
            __float2half_rn(v.w - __half2float(hw)));
    } else if (b < XB + WB) {
        int j = (b - XB) * 256 + t;
        int k = j / C1, n = j % C1;
        float v = W1[j];
        __half h = __float2half_rn(v);
        g_wth[n * FIN + k] = h;
        g_wtl[n * FIN + k] = __float2half_rn(v - __half2float(h));
    } else if (t < 32) {
        int hi = ei[2 * t + 1];
        unsigned bl = __ballot_sync(0xffffffffu, hi == 0);
        if (t == 0) g_is64 = (bl == 0xffffffffu) ? 1 : 0;
    }
}

// ---------------- CSR build ---------------------------------------------------
__global__ void k_count(const void* ei) {
    int p = blockIdx.x * blockDim.x + threadIdx.x;
    if (p >= TE / 2) return;
    int d0, d1;
    if (2 * p < EE) {
        if (g_is64) {
            longlong2 v = ((const longlong2*)ei)[EE / 2 + p];
            d0 = (int)v.x; d1 = (int)v.y;
        } else {
            int2 v = ((const int2*)ei)[EE / 2 + p];
            d0 = v.x; d1 = v.y;
        }
    } else {
        d0 = 2 * p - EE; d1 = d0 + 1;
    }
    if (d0 == d1) atomicAdd(&g_cnt[d0], 2);
    else { atomicAdd(&g_cnt[d0], 1); atomicAdd(&g_cnt[d1], 1); }
}

__global__ void k_scanA() {
    int t = threadIdx.x, b = blockIdx.x;
    int i = b * 256 + t;
    int v = (i < NN) ? g_cnt[i] : 0;
    int lane = t & 31, wid = t >> 5;
    int incl = v;
    #pragma unroll
    for (int o = 1; o < 32; o <<= 1) {
        int x = __shfl_up_sync(0xffffffffu, incl, o);
        if (lane >= o) incl += x;
    }
    __shared__ int ws[8];
    if (lane == 31) ws[wid] = incl;
    __syncthreads();
    if (t < 8) {
        int wv = ws[t];
        int wincl = wv;
        #pragma unroll
        for (int o = 1; o < 8; o <<= 1) {
            int x = __shfl_up_sync(0x000000ffu, wincl, o);
            if (t >= o) wincl += x;
        }
        ws[t] = wincl - wv;
        if (t == 7) g_bsum[b] = wincl;
    }
    __syncthreads();
    incl += ws[wid];
    if (i < NN) g_off[i + 1] = incl;
}

__global__ void k_scanC() {
    __shared__ int carry_s;
    int t = threadIdx.x, b = blockIdx.x;
    if (t < 32) {
        int c = 0;
        for (int i = t; i < b; i += 32) c += g_bsum[i];
        #pragma unroll
        for (int o = 16; o >= 1; o >>= 1) c += __shfl_xor_sync(0xffffffffu, c, o);
        if (t == 0) carry_s = c;
    }
    __syncthreads();
    if (b == 0 && t == 0) g_off[0] = 0;
    int i = b * 256 + t;
    if (i >= NN) return;
    int off = carry_s + g_off[i + 1];
    g_off[i + 1] = off;
    g_cur[i] = off - g_cnt[i];
}

__global__ void k_scatter(const void* ei) {
    int p = blockIdx.x * blockDim.x + threadIdx.x;
    if (p >= TE / 2) return;
    int s0, s1, d0, d1;
    if (2 * p < EE) {
        if (g_is64) {
            longlong2 sv = ((const longlong2*)ei)[p];
            longlong2 dv = ((const longlong2*)ei)[EE / 2 + p];
            s0 = (int)sv.x; s1 = (int)sv.y;
            d0 = (int)dv.x; d1 = (int)dv.y;
        } else {
            int2 sv = ((const int2*)ei)[p];
            int2 dv = ((const int2*)ei)[EE / 2 + p];
            s0 = sv.x; s1 = sv.y;
            d0 = dv.x; d1 = dv.y;
        }
    } else {
        s0 = d0 = 2 * p - EE;
        s1 = d1 = s0 + 1;
    }
    if (d0 == d1) {
        int pos = atomicAdd(&g_cur[d0], 2);
        g_csr[pos] = s0;
        g_csr[pos + 1] = s1;
    } else {
        g_csr[atomicAdd(&g_cur[d0], 1)] = s0;
        g_csr[atomicAdd(&g_cur[d1], 1)] = s1;
    }
}

// ---------------- mma + ldmatrix helpers --------------------------------------
__device__ __forceinline__ void mma_f16(float c[4], const uint32_t a[4], const uint32_t b[2]) {
    asm("mma.sync.aligned.m16n8k16.row.col.f32.f16.f16.f32 "
        "{%0,%1,%2,%3},{%4,%5,%6,%7},{%8,%9},{%0,%1,%2,%3};"
        : "+f"(c[0]), "+f"(c[1]), "+f"(c[2]), "+f"(c[3])
        : "r"(a[0]), "r"(a[1]), "r"(a[2]), "r"(a[3]), "r"(b[0]), "r"(b[1]));
}
__device__ __forceinline__ void ldsm_x4(uint32_t r[4], uint32_t saddr) {
    asm volatile("ldmatrix.sync.aligned.m8n8.x4.shared.b16 {%0,%1,%2,%3}, [%4];"
                 : "=r"(r[0]), "=r"(r[1]), "=r"(r[2]), "=r"(r[3]) : "r"(saddr));
}

// ---------------- GEMM1: h1 = x @ W1 via fp16x3 split, ldmatrix, prefetch ----
// grid (157, 8) ; block 256 = 8 warps (4 m x 2 n); BM=128 BN=64 BK=32
// A smem [m][k] stride 40; B smem [n][k] stride 40 ([n][k] is col-major for
// mma.row.col, so B fragments use NON-trans ldmatrix).
#define SAH 40
#define SBH 40
__global__ void __launch_bounds__(256, 3)
k_gemm1(const float* __restrict__ att_s, const float* __restrict__ att_d) {
    __shared__ __align__(16) __half sAh[128 * SAH];   // 10.0 KB
    __shared__ __align__(16) __half sAl[128 * SAH];
    __shared__ __align__(16) __half sBh[64 * SBH];    // 5.0 KB
    __shared__ __align__(16) __half sBl[64 * SBH];
    __shared__ float parts[128][2];
    __shared__ float partd[128][2];

    int tid = threadIdx.x;
    int warp = tid >> 5, lane = tid & 31;
    int wm = (warp >> 1) * 32;
    int wnidx = warp & 1;
    int wn = wnidx * 32;
    int row0 = blockIdx.x * 128;
    int head = blockIdx.y;
    int col0 = head * 64;

    float acc[2][4][4];
    #pragma unroll
    for (int i = 0; i < 2; i++)
        #pragma unroll
        for (int j = 0; j < 4; j++)
            #pragma unroll
            for (int q = 0; q < 4; q++) acc[i][j][q] = 0.f;

    // per-thread tile-fill coordinates
    int am0 = tid >> 2, aq0 = tid & 3;          // A row/quad, +64 rows for 2nd
    int bn0 = tid >> 2, bq0 = tid & 3;          // B row/quad
    // prefetch registers
    uint4 pAh0, pAh1, pAl0, pAl1, pBh, pBl;

    // ldmatrix source coordinates (per-lane)
    // A x4: matrices (m0-7,klo),(m8-15,klo),(m0-7,khi),(m8-15,khi)
    int a_row = (lane & 15), a_k8 = (lane >> 4) * 8;
    // B x4 (non-trans): matrices (nf even,klo),(nf even,khi),(nf odd,klo),(nf odd,khi)
    int b_row = wn + ((lane >> 4) & 1) * 8 + (lane & 7);
    int b_k8 = ((lane >> 3) & 1) * 8;

    auto load_chunk = [&](int chunk) {
        size_t kk = chunk * 32;
        size_t gA0 = (size_t)(row0 + am0) * FIN + kk + aq0 * 8;
        size_t gA1 = (size_t)(row0 + am0 + 64) * FIN + kk + aq0 * 8;
        bool ok0 = (row0 + am0) < NN, ok1 = (row0 + am0 + 64) < NN;
        pAh0 = ok0 ? *(const uint4*)&g_xhp[gA0] : make_uint4(0, 0, 0, 0);
        pAl0 = ok0 ? *(const uint4*)&g_xlp[gA0] : make_uint4(0, 0, 0, 0);
        pAh1 = ok1 ? *(const uint4*)&g_xhp[gA1] : make_uint4(0, 0, 0, 0);
        pAl1 = ok1 ? *(const uint4*)&g_xlp[gA1] : make_uint4(0, 0, 0, 0);
        size_t gB = (size_t)(col0 + bn0) * FIN + kk + bq0 * 8;
        pBh = *(const uint4*)&g_wth[gB];
        pBl = *(const uint4*)&g_wtl[gB];
    };
    auto store_chunk = [&]() {
        *(uint4*)&sAh[am0 * SAH + aq0 * 8] = pAh0;
        *(uint4*)&sAl[am0 * SAH + aq0 * 8] = pAl0;
        *(uint4*)&sAh[(am0 + 64) * SAH + aq0 * 8] = pAh1;
        *(uint4*)&sAl[(am0 + 64) * SAH + aq0 * 8] = pAl1;
        *(uint4*)&sBh[bn0 * SBH + bq0 * 8] = pBh;
        *(uint4*)&sBl[bn0 * SBH + bq0 * 8] = pBl;
    };

    load_chunk(0);
    store_chunk();
    __syncthreads();

    for (int chunk = 0; chunk < 4; chunk++) {
        if (chunk < 3) load_chunk(chunk + 1);

        #pragma unroll
        for (int ks = 0; ks < 2; ks++) {
            int kb = ks * 16;
            uint32_t ah[2][4], al[2][4];
            #pragma unroll
            for (int mf = 0; mf < 2; mf++) {
                int mb = wm + mf * 16;
                uint32_t sa = (uint32_t)__cvta_generic_to_shared(
                    &sAh[(mb + a_row) * SAH + kb + a_k8]);
                ldsm_x4(ah[mf], sa);
                uint32_t sl = (uint32_t)__cvta_generic_to_shared(
                    &sAl[(mb + a_row) * SAH + kb + a_k8]);
                ldsm_x4(al[mf], sl);
            }
            // B: non-trans x4 covers two nf blocks (klo+khi each)
            uint32_t bh[4][2], bl[4][2];
            #pragma unroll
            for (int p = 0; p < 2; p++) {
                uint32_t r[4];
                uint32_t sb = (uint32_t)__cvta_generic_to_shared(
                    &sBh[(b_row + p * 16) * SBH + kb + b_k8]);
                ldsm_x4(r, sb);
                bh[2 * p][0] = r[0]; bh[2 * p][1] = r[1];
                bh[2 * p + 1][0] = r[2]; bh[2 * p + 1][1] = r[3];
                uint32_t sb2 = (uint32_t)__cvta_generic_to_shared(
                    &sBl[(b_row + p * 16) * SBH + kb + b_k8]);
                ldsm_x4(r, sb2);
                bl[2 * p][0] = r[0]; bl[2 * p][1] = r[1];
                bl[2 * p + 1][0] = r[2]; bl[2 * p + 1][1] = r[3];
            }
            #pragma unroll
            for (int mf = 0; mf < 2; mf++)
                #pragma unroll
                for (int nf = 0; nf < 4; nf++) {
                    mma_f16(acc[mf][nf], ah[mf], bh[nf]);
                    mma_f16(acc[mf][nf], ah[mf], bl[nf]);
                    mma_f16(acc[mf][nf], al[mf], bh[nf]);
                }
        }
        __syncthreads();
        if (chunk < 3) {
            store_chunk();
            __syncthreads();
        }
    }

    // ---- epilogue: store h1 (fp16) + fused attention dots ------------------
    float asv[4][2], adv[4][2];
    #pragma unroll
    for (int nf = 0; nf < 4; nf++) {
        int cb = head * HID + wn + nf * 8 + 2 * (lane & 3);
        asv[nf][0] = att_s[cb];     asv[nf][1] = att_s[cb + 1];
        adv[nf][0] = att_d[cb];     adv[nf][1] = att_d[cb + 1];
    }

    #pragma unroll
    for (int mf = 0; mf < 2; mf++) {
        int rA = row0 + wm + mf * 16 + (lane >> 2);
        int rB = rA + 8;
        float ps0 = 0.f, pd0 = 0.f, ps1 = 0.f, pd1 = 0.f;
        #pragma unroll
        for (int nf = 0; nf < 4; nf++) {
            int cb = col0 + wn + nf * 8 + 2 * (lane & 3);
            if (rA < NN)
                *(__half2*)&g_h1[(size_t)rA * C1 + cb] =
                    __floats2half2_rn(acc[mf][nf][0], acc[mf][nf][1]);
            if (rB < NN)
                *(__half2*)&g_h1[(size_t)rB * C1 + cb] =
                    __floats2half2_rn(acc[mf][nf][2], acc[mf][nf][3]);
            ps0 += acc[mf][nf][0] * asv[nf][0] + acc[mf][nf][1] * asv[nf][1];
            pd0 += acc[mf][nf][0] * adv[nf][0] + acc[mf][nf][1] * adv[nf][1];
            ps1 += acc[mf][nf][2] * asv[nf][0] + acc[mf][nf][3] * asv[nf][1];
            pd1 += acc[mf][nf][2] * adv[nf][0] + acc[mf][nf][3] * adv[nf][1];
        }
        #pragma unroll
        for (int o = 1; o <= 2; o <<= 1) {
            ps0 += __shfl_xor_sync(0xffffffffu, ps0, o);
            pd0 += __shfl_xor_sync(0xffffffffu, pd0, o);
            ps1 += __shfl_xor_sync(0xffffffffu, ps1, o);
            pd1 += __shfl_xor_sync(0xffffffffu, pd1, o);
        }
        if ((lane & 3) == 0) {
            int lr0 = wm + mf * 16 + (lane >> 2);
            parts[lr0][wnidx] = ps0;
            partd[lr0][wnidx] = pd0;
            parts[lr0 + 8][wnidx] = ps1;
            partd[lr0 + 8][wnidx] = pd1;
        }
    }
    __syncthreads();
    if (tid < 128) {
        int grow = row0 + tid;
        if (grow < NN) {
            g_as1[grow * HEADS + head] = parts[tid][0] + parts[tid][1];
            g_ad1[grow * HEADS + head] = partd[tid][0] + partd[tid][1];
        }
    }
}

// ---------------- layer-1 aggregation (fp16 gathers) + fused layer-2 GEMM ----
__device__ __forceinline__ void acc_u4(float* acc, const uint4& u, float w) {
    float2 f0 = __half22float2(*(const __half2*)&u.x);
    float2 f1 = __half22float2(*(const __half2*)&u.y);
    float2 f2 = __half22float2(*(const __half2*)&u.z);
    float2 f3 = __half22float2(*(const __half2*)&u.w);
    acc[0] += w * f0.x; acc[1] += w * f0.y;
    acc[2] += w * f1.x; acc[3] += w * f1.y;
    acc[4] += w * f2.x; acc[5] += w * f2.y;
    acc[6] += w * f3.x; acc[7] += w * f3.y;
}

__global__ void k_agg1(const float* __restrict__ b1, const float* __restrict__ W2,
                       const float* __restrict__ att_s2, const float* __restrict__ att_d2) {
    __shared__ float sW2[C1 * 2];
    __shared__ float sb1[C1];
    int tid = threadIdx.x;
    for (int j = tid; j < C1 * 2; j += 256) sW2[j] = W2[j];
    for (int j = tid; j < C1; j += 256) sb1[j] = b1[j];
    __syncthreads();

    int node = (blockIdx.x * 256 + tid) >> 5;
    if (node >= NN) return;
    int lane = tid & 31;
    int head = lane >> 2;

    int beg = g_off[node], end = g_off[node + 1];
    float adst = (lane < 8) ? g_ad1[node * HEADS + lane] : 0.f;

    float s = 0.f;
    float acc[16];
    #pragma unroll
    for (int j = 0; j < 16; j++) acc[j] = 0.f;

    int e = beg;
    for (; e + 1 < end; e += 2) {
        int s0 = g_csr[e], s1 = g_csr[e + 1];
        float w0h = 0.f, w1h = 0.f;
        if (lane < 8) {
            float al0 = g_as1[s0 * HEADS + lane] + adst;
            float al1 = g_as1[s1 * HEADS + lane] + adst;
            al0 = al0 > 0.f ? al0 : 0.2f * al0;
            al1 = al1 > 0.f ? al1 : 0.2f * al1;
            w0h = __expf(al0);
            w1h = __expf(al1);
            s += w0h + w1h;
        }
        float w0 = __shfl_sync(0xffffffffu, w0h, head);
        float w1 = __shfl_sync(0xffffffffu, w1h, head);
        const uint4* hp0 = (const uint4*)(g_h1 + (size_t)s0 * C1 + lane * 16);
        const uint4* hp1 = (const uint4*)(g_h1 + (size_t)s1 * C1 + lane * 16);
        uint4 u00 = hp0[0], u01 = hp0[1];
        uint4 u10 = hp1[0], u11 = hp1[1];
        acc_u4(acc,     u00, w0);
        acc_u4(acc + 8, u01, w0);
        acc_u4(acc,     u10, w1);
        acc_u4(acc + 8, u11, w1);
    }
    if (e < end) {
        int s0 = g_csr[e];
        float w0h = 0.f;
        if (lane < 8) {
            float al0 = g_as1[s0 * HEADS + lane] + adst;
            al0 = al0 > 0.f ? al0 : 0.2f * al0;
            w0h = __expf(al0);
            s += w0h;
        }
        float w0 = __shfl_sync(0xffffffffu, w0h, head);
        const uint4* hp0 = (const uint4*)(g_h1 + (size_t)s0 * C1 + lane * 16);
        uint4 u00 = hp0[0], u01 = hp0[1];
        acc_u4(acc,     u00, w0);
        acc_u4(acc + 8, u01, w0);
    }

    float inv_h = (lane < 8) ? (1.f / s) : 0.f;
    float inv = __shfl_sync(0xffffffffu, inv_h, head);

    float p0 = 0.f, p1 = 0.f;
    #pragma unroll
    for (int j = 0; j < 16; j++) {
        int ch = lane * 16 + j;
        float o = acc[j] * inv + sb1[ch];
        float he = o > 0.f ? o : expm1f(o);
        p0 += he * sW2[ch * 2 + 0];
        p1 += he * sW2[ch * 2 + 1];
    }
    #pragma unroll
    for (int off = 16; off >= 1; off >>= 1) {
        p0 += __shfl_xor_sync(0xffffffffu, p0, off);
        p1 += __shfl_xor_sync(0xffffffffu, p1, off);
    }
    if (lane == 0) {
        g_h2[node * 2 + 0] = p0;
        g_h2[node * 2 + 1] = p1;
        g_as2[node] = p0 * att_s2[0] + p1 * att_s2[1];
        g_ad2[node] = p0 * att_d2[0] + p1 * att_d2[1];
    }
}

// ---------------- layer-2 aggregation ----------------------------------------
__global__ void k_agg2(const float* __restrict__ b2, float* __restrict__ out) {
    int tid = threadIdx.x;
    int node = (blockIdx.x * 256 + tid) >> 5;
    if (node >= NN) return;
    int lane = tid & 31;

    int beg = g_off[node], end = g_off[node + 1];
    float adst = g_ad2[node];

    float s = 0.f, a0 = 0.f, a1 = 0.f;
    for (int e = beg + lane; e < end; e += 32) {
        int src = g_csr[e];
        float al = g_as2[src] + adst;
        al = al > 0.f ? al : 0.2f * al;
        float w = __expf(al);
        s  += w;
        a0 += w * g_h2[src * 2 + 0];
        a1 += w * g_h2[src * 2 + 1];
    }
    #pragma unroll
    for (int off = 16; off >= 1; off >>= 1) {
        s  += __shfl_xor_sync(0xffffffffu, s,  off);
        a0 += __shfl_xor_sync(0xffffffffu, a0, off);
        a1 += __shfl_xor_sync(0xffffffffu, a1, off);
    }
    if (lane == 0) {
        float inv = 1.f / s;
        out[node * 2 + 0] = a0 * inv + b2[0];
        out[node * 2 + 1] = a1 * inv + b2[1];
    }
}

// ---------------- launch ------------------------------------------------------
extern "C" void kernel_launch(void* const* d_in, const int* in_sizes, int n_in,
                              void* d_out, int out_size) {
    const float* x   = (const float*)d_in[0];
    const void*  ei  = d_in[1];
    const float* W1  = (const float*)d_in[2];
    const float* as1 = (const float*)d_in[3];
    const float* ad1 = (const float*)d_in[4];
    const float* b1  = (const float*)d_in[5];
    const float* W2  = (const float*)d_in[6];
    const float* as2 = (const float*)d_in[7];
    const float* ad2 = (const float*)d_in[8];
    const float* b2  = (const float*)d_in[9];
    float* out = (float*)d_out;

    k_prep<<<XB + WB + 1, 256>>>(x, W1, (const int*)ei);                   // 0
    k_count<<<(TE / 2 + 255) / 256, 256>>>(ei);                            // 1
    k_scanA<<<NBLK, 256>>>();                                              // 2
    k_gemm1<<<dim3((NN + 127) / 128, HEADS), 256>>>(as1, ad1);             // 3 <- profiled
    k_scanC<<<NBLK, 256>>>();                                              // 4
    k_scatter<<<(TE / 2 + 255) / 256, 256>>>(ei);                          // 5
    k_agg1<<<(NN * 32 + 255) / 256, 256>>>(b1, W2, as2, ad2);              // 6
    k_agg2<<<(NN * 32 + 255) / 256, 256>>>(b2, out);                       // 7
}

// round 10
// speedup vs baseline: 1.1494x; 1.1494x over previous
#include <cuda_runtime.h>
#include <cuda_fp16.h>
#include <cstdint>

#define NN 20000
#define EE 320000
#define TE (EE + NN)          // edges + self loops
#define FIN 128
#define HID 64
#define HEADS 8
#define C1 (HEADS * HID)      // 512
#define NBLK ((NN + 255) / 256)   // 79 scan blocks
#define XB (NN * FIN / 4 / 256)   // 2500 split_x blocks
#define WB (FIN * C1 / 256)       // 256 split_w blocks

// ---------------- scratch (static device globals; no allocation) -------------
__device__ int    g_is64;
__device__ int    g_cnt[NN];
__device__ int    g_off[NN + 1];
__device__ int    g_cur[NN];
__device__ int    g_csr[TE];
__device__ int    g_bsum[NBLK];
__device__ __half g_h1[(size_t)NN * C1];      // 20 MB, fp16 features
__device__ __half g_xhp[(size_t)NN * FIN];    // fp16 x (hi only)   [N][128]
__device__ __half g_wth[C1 * FIN];            // W1^T hi plane      [n][k]
__device__ __half g_wtl[C1 * FIN];            // W1^T lo plane
__device__ float  g_as1[NN * HEADS];
__device__ float  g_ad1[NN * HEADS];
__device__ float  g_h2[NN * 2];
__device__ float  g_as2[NN];
__device__ float  g_ad2[NN];

// ---------------- fused prep: x->fp16 + split_w + detect + zero cnt ----------
__global__ void k_prep(const float* __restrict__ x, const float* __restrict__ W1,
                       const int* __restrict__ ei) {
    int b = blockIdx.x, t = threadIdx.x;
    if (b < XB) {
        int i = b * 256 + t;
        if (i < NN) g_cnt[i] = 0;
        float4 v = ((const float4*)x)[i];
        ((__half2*)g_xhp)[2 * i + 0] = __floats2half2_rn(v.x, v.y);
        ((__half2*)g_xhp)[2 * i + 1] = __floats2half2_rn(v.z, v.w);
    } else if (b < XB + WB) {
        int j = (b - XB) * 256 + t;
        int k = j / C1, n = j % C1;
        float v = W1[j];
        __half h = __float2half_rn(v);
        g_wth[n * FIN + k] = h;
        g_wtl[n * FIN + k] = __float2half_rn(v - __half2float(h));
    } else if (t < 32) {
        int hi = ei[2 * t + 1];
        unsigned bl = __ballot_sync(0xffffffffu, hi == 0);
        if (t == 0) g_is64 = (bl == 0xffffffffu) ? 1 : 0;
    }
}

// ---------------- CSR build ---------------------------------------------------
__global__ void k_count(const void* ei) {
    int p = blockIdx.x * blockDim.x + threadIdx.x;
    if (p >= TE / 2) return;
    int d0, d1;
    if (2 * p < EE) {
        if (g_is64) {
            longlong2 v = ((const longlong2*)ei)[EE / 2 + p];
            d0 = (int)v.x; d1 = (int)v.y;
        } else {
            int2 v = ((const int2*)ei)[EE / 2 + p];
            d0 = v.x; d1 = v.y;
        }
    } else {
        d0 = 2 * p - EE; d1 = d0 + 1;
    }
    if (d0 == d1) atomicAdd(&g_cnt[d0], 2);
    else { atomicAdd(&g_cnt[d0], 1); atomicAdd(&g_cnt[d1], 1); }
}

__global__ void k_scanA() {
    int t = threadIdx.x, b = blockIdx.x;
    int i = b * 256 + t;
    int v = (i < NN) ? g_cnt[i] : 0;
    int lane = t & 31, wid = t >> 5;
    int incl = v;
    #pragma unroll
    for (int o = 1; o < 32; o <<= 1) {
        int x = __shfl_up_sync(0xffffffffu, incl, o);
        if (lane >= o) incl += x;
    }
    __shared__ int ws[8];
    if (lane == 31) ws[wid] = incl;
    __syncthreads();
    if (t < 8) {
        int wv = ws[t];
        int wincl = wv;
        #pragma unroll
        for (int o = 1; o < 8; o <<= 1) {
            int x = __shfl_up_sync(0x000000ffu, wincl, o);
            if (t >= o) wincl += x;
        }
        ws[t] = wincl - wv;
        if (t == 7) g_bsum[b] = wincl;
    }
    __syncthreads();
    incl += ws[wid];
    if (i < NN) g_off[i + 1] = incl;
}

__global__ void k_scanC() {
    __shared__ int carry_s;
    int t = threadIdx.x, b = blockIdx.x;
    if (t < 32) {
        int c = 0;
        for (int i = t; i < b; i += 32) c += g_bsum[i];
        #pragma unroll
        for (int o = 16; o >= 1; o >>= 1) c += __shfl_xor_sync(0xffffffffu, c, o);
        if (t == 0) carry_s = c;
    }
    __syncthreads();
    if (b == 0 && t == 0) g_off[0] = 0;
    int i = b * 256 + t;
    if (i >= NN) return;
    int off = carry_s + g_off[i + 1];
    g_off[i + 1] = off;
    g_cur[i] = off - g_cnt[i];
}

__global__ void k_scatter(const void* ei) {
    int p = blockIdx.x * blockDim.x + threadIdx.x;
    if (p >= TE / 2) return;
    int s0, s1, d0, d1;
    if (2 * p < EE) {
        if (g_is64) {
            longlong2 sv = ((const longlong2*)ei)[p];
            longlong2 dv = ((const longlong2*)ei)[EE / 2 + p];
            s0 = (int)sv.x; s1 = (int)sv.y;
            d0 = (int)dv.x; d1 = (int)dv.y;
        } else {
            int2 sv = ((const int2*)ei)[p];
            int2 dv = ((const int2*)ei)[EE / 2 + p];
            s0 = sv.x; s1 = sv.y;
            d0 = dv.x; d1 = dv.y;
        }
    } else {
        s0 = d0 = 2 * p - EE;
        s1 = d1 = s0 + 1;
    }
    if (d0 == d1) {
        int pos = atomicAdd(&g_cur[d0], 2);
        g_csr[pos] = s0;
        g_csr[pos + 1] = s1;
    } else {
        g_csr[atomicAdd(&g_cur[d0], 1)] = s0;
        g_csr[atomicAdd(&g_cur[d1], 1)] = s1;
    }
}

// ---------------- fp16 mma -----------------------------------------------------
__device__ __forceinline__ void mma_f16(float c[4], const uint32_t a[4], const uint32_t b[2]) {
    asm("mma.sync.aligned.m16n8k16.row.col.f32.f16.f16.f32 "
        "{%0,%1,%2,%3},{%4,%5,%6,%7},{%8,%9},{%0,%1,%2,%3};"
        : "+f"(c[0]), "+f"(c[1]), "+f"(c[2]), "+f"(c[3])
        : "r"(a[0]), "r"(a[1]), "r"(a[2]), "r"(a[3]), "r"(b[0]), "r"(b[1]));
}

// ---------------- GEMM1: h1 = fp16(x) @ (W1h + W1l), fused att epilogue ------
// grid (157, 8) ; block 256 = 8 warps (4 m x 2 n); BM=128 BN=64 BK=32
// warp tile 32x32 (2 mf x 4 nf). A smem [m][k] stride 40 halfs (x fp16, exact);
// B smem [n][k] stride 40 halfs, hi+lo planes. 2 MMA terms: Ah*Bh + Ah*Bl.
#define SAH 40
#define SBH 40
__global__ void __launch_bounds__(256, 3)
k_gemm1(const float* __restrict__ att_s, const float* __restrict__ att_d) {
    __shared__ __align__(16) __half sAh[128 * SAH];   // 10.0 KB
    __shared__ __align__(16) __half sBh[64 * SBH];    // 5.0 KB
    __shared__ __align__(16) __half sBl[64 * SBH];
    __shared__ float parts[128][2];
    __shared__ float partd[128][2];

    int tid = threadIdx.x;
    int warp = tid >> 5, lane = tid & 31;
    int wm = (warp >> 1) * 32;
    int wnidx = warp & 1;
    int wn = wnidx * 32;
    int row0 = blockIdx.x * 128;
    int head = blockIdx.y;
    int col0 = head * 64;

    float acc[2][4][4];
    #pragma unroll
    for (int i = 0; i < 2; i++)
        #pragma unroll
        for (int j = 0; j < 4; j++)
            #pragma unroll
            for (int q = 0; q < 4; q++) acc[i][j][q] = 0.f;

    int ar = lane >> 2, ac = lane & 3;

    for (int chunk = 0; chunk < 4; chunk++) {
        int kk = chunk * 32;
        // fill A: 128 rows x 32 halfs = 512 uint4, 2 per thread
        #pragma unroll
        for (int r = 0; r < 2; r++) {
            int idx = tid + 256 * r;
            int m = idx >> 2, q = idx & 3;
            int grow = row0 + m;
            uint4 vh = make_uint4(0u, 0u, 0u, 0u);
            if (grow < NN)
                vh = *(const uint4*)&g_xhp[(size_t)grow * FIN + kk + q * 8];
            *(uint4*)&sAh[m * SAH + q * 8] = vh;
        }
        // fill B: 64 n-rows x 32 halfs per plane = 256 uint4 per plane, 1/thread
        {
            int n = tid >> 2, q = tid & 3;
            size_t g = (size_t)(col0 + n) * FIN + kk + q * 8;
            *(uint4*)&sBh[n * SBH + q * 8] = *(const uint4*)&g_wth[g];
            *(uint4*)&sBl[n * SBH + q * 8] = *(const uint4*)&g_wtl[g];
        }
        __syncthreads();

        #pragma unroll
        for (int ks = 0; ks < 2; ks++) {
            int kb = ks * 16;
            uint32_t ah[2][4];
            #pragma unroll
            for (int mf = 0; mf < 2; mf++) {
                int mb = wm + mf * 16;
                int i0 = (mb + ar) * SAH + kb + 2 * ac;
                int i1 = (mb + ar + 8) * SAH + kb + 2 * ac;
                ah[mf][0] = *(const uint32_t*)&sAh[i0];
                ah[mf][1] = *(const uint32_t*)&sAh[i1];
                ah[mf][2] = *(const uint32_t*)&sAh[i0 + 8];
                ah[mf][3] = *(const uint32_t*)&sAh[i1 + 8];
            }
            uint32_t bh[4][2], bl[4][2];
            #pragma unroll
            for (int nf = 0; nf < 4; nf++) {
                int col = wn + nf * 8 + (lane >> 2);
                int i0 = col * SBH + kb + 2 * (lane & 3);
                bh[nf][0] = *(const uint32_t*)&sBh[i0];
                bh[nf][1] = *(const uint32_t*)&sBh[i0 + 8];
                bl[nf][0] = *(const uint32_t*)&sBl[i0];
                bl[nf][1] = *(const uint32_t*)&sBl[i0 + 8];
            }
            #pragma unroll
            for (int mf = 0; mf < 2; mf++)
                #pragma unroll
                for (int nf = 0; nf < 4; nf++) {
                    mma_f16(acc[mf][nf], ah[mf], bh[nf]);
                    mma_f16(acc[mf][nf], ah[mf], bl[nf]);
                }
        }
        __syncthreads();
    }

    // ---- epilogue: store h1 (fp16) + fused attention dots ------------------
    float asv[4][2], adv[4][2];
    #pragma unroll
    for (int nf = 0; nf < 4; nf++) {
        int cb = head * HID + wn + nf * 8 + 2 * (lane & 3);
        asv[nf][0] = att_s[cb];     asv[nf][1] = att_s[cb + 1];
        adv[nf][0] = att_d[cb];     adv[nf][1] = att_d[cb + 1];
    }

    #pragma unroll
    for (int mf = 0; mf < 2; mf++) {
        int rA = row0 + wm + mf * 16 + (lane >> 2);
        int rB = rA + 8;
        float ps0 = 0.f, pd0 = 0.f, ps1 = 0.f, pd1 = 0.f;
        #pragma unroll
        for (int nf = 0; nf < 4; nf++) {
            int cb = col0 + wn + nf * 8 + 2 * (lane & 3);
            if (rA < NN)
                *(__half2*)&g_h1[(size_t)rA * C1 + cb] =
                    __floats2half2_rn(acc[mf][nf][0], acc[mf][nf][1]);
            if (rB < NN)
                *(__half2*)&g_h1[(size_t)rB * C1 + cb] =
                    __floats2half2_rn(acc[mf][nf][2], acc[mf][nf][3]);
            ps0 += acc[mf][nf][0] * asv[nf][0] + acc[mf][nf][1] * asv[nf][1];
            pd0 += acc[mf][nf][0] * adv[nf][0] + acc[mf][nf][1] * adv[nf][1];
            ps1 += acc[mf][nf][2] * asv[nf][0] + acc[mf][nf][3] * asv[nf][1];
            pd1 += acc[mf][nf][2] * adv[nf][0] + acc[mf][nf][3] * adv[nf][1];
        }
        #pragma unroll
        for (int o = 1; o <= 2; o <<= 1) {
            ps0 += __shfl_xor_sync(0xffffffffu, ps0, o);
            pd0 += __shfl_xor_sync(0xffffffffu, pd0, o);
            ps1 += __shfl_xor_sync(0xffffffffu, ps1, o);
            pd1 += __shfl_xor_sync(0xffffffffu, pd1, o);
        }
        if ((lane & 3) == 0) {
            int lr0 = wm + mf * 16 + (lane >> 2);
            parts[lr0][wnidx] = ps0;
            partd[lr0][wnidx] = pd0;
            parts[lr0 + 8][wnidx] = ps1;
            partd[lr0 + 8][wnidx] = pd1;
        }
    }
    __syncthreads();
    if (tid < 128) {
        int grow = row0 + tid;
        if (grow < NN) {
            g_as1[grow * HEADS + head] = parts[tid][0] + parts[tid][1];
            g_ad1[grow * HEADS + head] = partd[tid][0] + partd[tid][1];
        }
    }
}

// ---------------- layer-1 aggregation (fp16 gathers) + fused layer-2 GEMM ----
__device__ __forceinline__ void acc_u4(float* acc, const uint4& u, float w) {
    float2 f0 = __half22float2(*(const __half2*)&u.x);
    float2 f1 = __half22float2(*(const __half2*)&u.y);
    float2 f2 = __half22float2(*(const __half2*)&u.z);
    float2 f3 = __half22float2(*(const __half2*)&u.w);
    acc[0] += w * f0.x; acc[1] += w * f0.y;
    acc[2] += w * f1.x; acc[3] += w * f1.y;
    acc[4] += w * f2.x; acc[5] += w * f2.y;
    acc[6] += w * f3.x; acc[7] += w * f3.y;
}

__global__ void k_agg1(const float* __restrict__ b1, const float* __restrict__ W2,
                       const float* __restrict__ att_s2, const float* __restrict__ att_d2) {
    __shared__ float sW2[C1 * 2];
    __shared__ float sb1[C1];
    int tid = threadIdx.x;
    for (int j = tid; j < C1 * 2; j += 256) sW2[j] = W2[j];
    for (int j = tid; j < C1; j += 256) sb1[j] = b1[j];
    __syncthreads();

    int node = (blockIdx.x * 256 + tid) >> 5;
    if (node >= NN) return;
    int lane = tid & 31;
    int head = lane >> 2;

    int beg = g_off[node], end = g_off[node + 1];
    float adst = (lane < 8) ? g_ad1[node * HEADS + lane] : 0.f;

    float s = 0.f;
    float acc[16];
    #pragma unroll
    for (int j = 0; j < 16; j++) acc[j] = 0.f;

    int e = beg;
    for (; e + 1 < end; e += 2) {
        int s0 = g_csr[e], s1 = g_csr[e + 1];
        float w0h = 0.f, w1h = 0.f;
        if (lane < 8) {
            float al0 = g_as1[s0 * HEADS + lane] + adst;
            float al1 = g_as1[s1 * HEADS + lane] + adst;
            al0 = al0 > 0.f ? al0 : 0.2f * al0;
            al1 = al1 > 0.f ? al1 : 0.2f * al1;
            w0h = __expf(al0);
            w1h = __expf(al1);
            s += w0h + w1h;
        }
        float w0 = __shfl_sync(0xffffffffu, w0h, head);
        float w1 = __shfl_sync(0xffffffffu, w1h, head);
        const uint4* hp0 = (const uint4*)(g_h1 + (size_t)s0 * C1 + lane * 16);
        const uint4* hp1 = (const uint4*)(g_h1 + (size_t)s1 * C1 + lane * 16);
        uint4 u00 = hp0[0], u01 = hp0[1];
        uint4 u10 = hp1[0], u11 = hp1[1];
        acc_u4(acc,     u00, w0);
        acc_u4(acc + 8, u01, w0);
        acc_u4(acc,     u10, w1);
        acc_u4(acc + 8, u11, w1);
    }
    if (e < end) {
        int s0 = g_csr[e];
        float w0h = 0.f;
        if (lane < 8) {
            float al0 = g_as1[s0 * HEADS + lane] + adst;
            al0 = al0 > 0.f ? al0 : 0.2f * al0;
            w0h = __expf(al0);
            s += w0h;
        }
        float w0 = __shfl_sync(0xffffffffu, w0h, head);
        const uint4* hp0 = (const uint4*)(g_h1 + (size_t)s0 * C1 + lane * 16);
        uint4 u00 = hp0[0], u01 = hp0[1];
        acc_u4(acc,     u00, w0);
        acc_u4(acc + 8, u01, w0);
    }

    float inv_h = (lane < 8) ? (1.f / s) : 0.f;
    float inv = __shfl_sync(0xffffffffu, inv_h, head);

    float p0 = 0.f, p1 = 0.f;
    #pragma unroll
    for (int j = 0; j < 16; j++) {
        int ch = lane * 16 + j;
        float o = acc[j] * inv + sb1[ch];
        float he = o > 0.f ? o : expm1f(o);
        p0 += he * sW2[ch * 2 + 0];
        p1 += he * sW2[ch * 2 + 1];
    }
    #pragma unroll
    for (int off = 16; off >= 1; off >>= 1) {
        p0 += __shfl_xor_sync(0xffffffffu, p0, off);
        p1 += __shfl_xor_sync(0xffffffffu, p1, off);
    }
    if (lane == 0) {
        g_h2[node * 2 + 0] = p0;
        g_h2[node * 2 + 1] = p1;
        g_as2[node] = p0 * att_s2[0] + p1 * att_s2[1];
        g_ad2[node] = p0 * att_d2[0] + p1 * att_d2[1];
    }
}

// ---------------- layer-2 aggregation ----------------------------------------
__global__ void k_agg2(const float* __restrict__ b2, float* __restrict__ out) {
    int tid = threadIdx.x;
    int node = (blockIdx.x * 256 + tid) >> 5;
    if (node >= NN) return;
    int lane = tid & 31;

    int beg = g_off[node], end = g_off[node + 1];
    float adst = g_ad2[node];

    float s = 0.f, a0 = 0.f, a1 = 0.f;
    for (int e = beg + lane; e < end; e += 32) {
        int src = g_csr[e];
        float al = g_as2[src] + adst;
        al = al > 0.f ? al : 0.2f * al;
        float w = __expf(al);
        s  += w;
        a0 += w * g_h2[src * 2 + 0];
        a1 += w * g_h2[src * 2 + 1];
    }
    #pragma unroll
    for (int off = 16; off >= 1; off >>= 1) {
        s  += __shfl_xor_sync(0xffffffffu, s,  off);
        a0 += __shfl_xor_sync(0xffffffffu, a0, off);
        a1 += __shfl_xor_sync(0xffffffffu, a1, off);
    }
    if (lane == 0) {
        float inv = 1.f / s;
        out[node * 2 + 0] = a0 * inv + b2[0];
        out[node * 2 + 1] = a1 * inv + b2[1];
    }
}

// ---------------- launch ------------------------------------------------------
extern "C" void kernel_launch(void* const* d_in, const int* in_sizes, int n_in,
                              void* d_out, int out_size) {
    const float* x   = (const float*)d_in[0];
    const void*  ei  = d_in[1];
    const float* W1  = (const float*)d_in[2];
    const float* as1 = (const float*)d_in[3];
    const float* ad1 = (const float*)d_in[4];
    const float* b1  = (const float*)d_in[5];
    const float* W2  = (const float*)d_in[6];
    const float* as2 = (const float*)d_in[7];
    const float* ad2 = (const float*)d_in[8];
    const float* b2  = (const float*)d_in[9];
    float* out = (float*)d_out;

    k_prep<<<XB + WB + 1, 256>>>(x, W1, (const int*)ei);                   // 0
    k_count<<<(TE / 2 + 255) / 256, 256>>>(ei);                            // 1
    k_scanA<<<NBLK, 256>>>();                                              // 2
    k_gemm1<<<dim3((NN + 127) / 128, HEADS), 256>>>(as1, ad1);             // 3 <- profiled
    k_scanC<<<NBLK, 256>>>();                                              // 4
    k_scatter<<<(TE / 2 + 255) / 256, 256>>>(ei);                          // 5
    k_agg1<<<(NN * 32 + 255) / 256, 256>>>(b1, W2, as2, ad2);              // 6
    k_agg2<<<(NN * 32 + 255) / 256, 256>>>(b2, out);                       // 7
}

// round 11
// speedup vs baseline: 1.3213x; 1.1496x over previous
#include <cuda_runtime.h>
#include <cuda_fp16.h>
#include <cstdint>

#define NN 20000
#define EE 320000
#define TE (EE + NN)          // edges + self loops
#define FIN 128
#define HID 64
#define HEADS 8
#define C1 (HEADS * HID)      // 512
#define NBLK ((NN + 255) / 256)   // 79 scan blocks
#define XB (NN * FIN / 4 / 256)   // 2500 split_x blocks
#define WB (FIN * C1 / 256)       // 256 split_w blocks

// ---------------- scratch (static device globals; no allocation) -------------
__device__ int    g_is64;
__device__ int    g_cnt[NN];
__device__ int    g_off[NN + 1];
__device__ int    g_cur[NN];
__device__ int    g_csr[TE];
__device__ int    g_bsum[NBLK];
__device__ __half g_h1[(size_t)NN * C1];      // 20 MB, fp16 features
__device__ __half g_xhp[(size_t)NN * FIN];    // fp16 x            [N][128]
__device__ __half g_wth[C1 * FIN];            // fp16 W1^T         [n][k]
__device__ float  g_as1[NN * HEADS];
__device__ float  g_ad1[NN * HEADS];
__device__ float  g_h2[NN * 2];
__device__ float  g_as2[NN];
__device__ float  g_ad2[NN];

// ---------------- fused prep: x->fp16 + W1^T->fp16 + detect + zero cnt -------
__global__ void k_prep(const float* __restrict__ x, const float* __restrict__ W1,
                       const int* __restrict__ ei) {
    int b = blockIdx.x, t = threadIdx.x;
    if (b < XB) {
        int i = b * 256 + t;
        if (i < NN) g_cnt[i] = 0;
        float4 v = ((const float4*)x)[i];
        ((__half2*)g_xhp)[2 * i + 0] = __floats2half2_rn(v.x, v.y);
        ((__half2*)g_xhp)[2 * i + 1] = __floats2half2_rn(v.z, v.w);
    } else if (b < XB + WB) {
        int j = (b - XB) * 256 + t;
        int k = j / C1, n = j % C1;
        g_wth[n * FIN + k] = __float2half_rn(W1[j]);
    } else if (t < 32) {
        int hi = ei[2 * t + 1];
        unsigned bl = __ballot_sync(0xffffffffu, hi == 0);
        if (t == 0) g_is64 = (bl == 0xffffffffu) ? 1 : 0;
    }
}

// ---------------- CSR build ---------------------------------------------------
__global__ void k_count(const void* ei) {
    int p = blockIdx.x * blockDim.x + threadIdx.x;
    if (p >= TE / 2) return;
    int d0, d1;
    if (2 * p < EE) {
        if (g_is64) {
            longlong2 v = ((const longlong2*)ei)[EE / 2 + p];
            d0 = (int)v.x; d1 = (int)v.y;
        } else {
            int2 v = ((const int2*)ei)[EE / 2 + p];
            d0 = v.x; d1 = v.y;
        }
    } else {
        d0 = 2 * p - EE; d1 = d0 + 1;
    }
    if (d0 == d1) atomicAdd(&g_cnt[d0], 2);
    else { atomicAdd(&g_cnt[d0], 1); atomicAdd(&g_cnt[d1], 1); }
}

__global__ void k_scanA() {
    int t = threadIdx.x, b = blockIdx.x;
    int i = b * 256 + t;
    int v = (i < NN) ? g_cnt[i] : 0;
    int lane = t & 31, wid = t >> 5;
    int incl = v;
    #pragma unroll
    for (int o = 1; o < 32; o <<= 1) {
        int x = __shfl_up_sync(0xffffffffu, incl, o);
        if (lane >= o) incl += x;
    }
    __shared__ int ws[8];
    if (lane == 31) ws[wid] = incl;
    __syncthreads();
    if (t < 8) {
        int wv = ws[t];
        int wincl = wv;
        #pragma unroll
        for (int o = 1; o < 8; o <<= 1) {
            int x = __shfl_up_sync(0x000000ffu, wincl, o);
            if (t >= o) wincl += x;
        }
        ws[t] = wincl - wv;
        if (t == 7) g_bsum[b] = wincl;
    }
    __syncthreads();
    incl += ws[wid];
    if (i < NN) g_off[i + 1] = incl;
}

__global__ void k_scanC() {
    __shared__ int carry_s;
    int t = threadIdx.x, b = blockIdx.x;
    if (t < 32) {
        int c = 0;
        for (int i = t; i < b; i += 32) c += g_bsum[i];
        #pragma unroll
        for (int o = 16; o >= 1; o >>= 1) c += __shfl_xor_sync(0xffffffffu, c, o);
        if (t == 0) carry_s = c;
    }
    __syncthreads();
    if (b == 0 && t == 0) g_off[0] = 0;
    int i = b * 256 + t;
    if (i >= NN) return;
    int off = carry_s + g_off[i + 1];
    g_off[i + 1] = off;
    g_cur[i] = off - g_cnt[i];
}

__global__ void k_scatter(const void* ei) {
    int p = blockIdx.x * blockDim.x + threadIdx.x;
    if (p >= TE / 2) return;
    int s0, s1, d0, d1;
    if (2 * p < EE) {
        if (g_is64) {
            longlong2 sv = ((const longlong2*)ei)[p];
            longlong2 dv = ((const longlong2*)ei)[EE / 2 + p];
            s0 = (int)sv.x; s1 = (int)sv.y;
            d0 = (int)dv.x; d1 = (int)dv.y;
        } else {
            int2 sv = ((const int2*)ei)[p];
            int2 dv = ((const int2*)ei)[EE / 2 + p];
            s0 = sv.x; s1 = sv.y;
            d0 = dv.x; d1 = dv.y;
        }
    } else {
        s0 = d0 = 2 * p - EE;
        s1 = d1 = s0 + 1;
    }
    if (d0 == d1) {
        int pos = atomicAdd(&g_cur[d0], 2);
        g_csr[pos] = s0;
        g_csr[pos + 1] = s1;
    } else {
        g_csr[atomicAdd(&g_cur[d0], 1)] = s0;
        g_csr[atomicAdd(&g_cur[d1], 1)] = s1;
    }
}

// ---------------- fp16 mma -----------------------------------------------------
__device__ __forceinline__ void mma_f16(float c[4], const uint32_t a[4], const uint32_t b[2]) {
    asm("mma.sync.aligned.m16n8k16.row.col.f32.f16.f16.f32 "
        "{%0,%1,%2,%3},{%4,%5,%6,%7},{%8,%9},{%0,%1,%2,%3};"
        : "+f"(c[0]), "+f"(c[1]), "+f"(c[2]), "+f"(c[3])
        : "r"(a[0]), "r"(a[1]), "r"(a[2]), "r"(a[3]), "r"(b[0]), "r"(b[1]));
}

// ---------------- GEMM1: h1 = fp16(x) @ fp16(W1), fused att epilogue ---------
// grid (157, 8) ; block 256 = 8 warps (4 m x 2 n); BM=128 BN=64 BK=32
// warp tile 32x32 (2 mf x 4 nf). A smem [m][k] stride 40; B smem [n][k] stride 40.
#define SAH 40
#define SBH 40
__global__ void __launch_bounds__(256, 3)
k_gemm1(const float* __restrict__ att_s, const float* __restrict__ att_d) {
    __shared__ __align__(16) __half sAh[128 * SAH];   // 10.0 KB
    __shared__ __align__(16) __half sBh[64 * SBH];    // 5.0 KB
    __shared__ float parts[128][2];
    __shared__ float partd[128][2];

    int tid = threadIdx.x;
    int warp = tid >> 5, lane = tid & 31;
    int wm = (warp >> 1) * 32;
    int wnidx = warp & 1;
    int wn = wnidx * 32;
    int row0 = blockIdx.x * 128;
    int head = blockIdx.y;
    int col0 = head * 64;

    float acc[2][4][4];
    #pragma unroll
    for (int i = 0; i < 2; i++)
        #pragma unroll
        for (int j = 0; j < 4; j++)
            #pragma unroll
            for (int q = 0; q < 4; q++) acc[i][j][q] = 0.f;

    int ar = lane >> 2, ac = lane & 3;

    for (int chunk = 0; chunk < 4; chunk++) {
        int kk = chunk * 32;
        // fill A: 128 rows x 32 halfs = 512 uint4, 2 per thread
        #pragma unroll
        for (int r = 0; r < 2; r++) {
            int idx = tid + 256 * r;
            int m = idx >> 2, q = idx & 3;
            int grow = row0 + m;
            uint4 vh = make_uint4(0u, 0u, 0u, 0u);
            if (grow < NN)
                vh = *(const uint4*)&g_xhp[(size_t)grow * FIN + kk + q * 8];
            *(uint4*)&sAh[m * SAH + q * 8] = vh;
        }
        // fill B: 64 n-rows x 32 halfs = 256 uint4, 1 per thread
        {
            int n = tid >> 2, q = tid & 3;
            if (tid < 256) {
                size_t g = (size_t)(col0 + n) * FIN + kk + q * 8;
                *(uint4*)&sBh[n * SBH + q * 8] = *(const uint4*)&g_wth[g];
            }
        }
        __syncthreads();

        #pragma unroll
        for (int ks = 0; ks < 2; ks++) {
            int kb = ks * 16;
            uint32_t ah[2][4];
            #pragma unroll
            for (int mf = 0; mf < 2; mf++) {
                int mb = wm + mf * 16;
                int i0 = (mb + ar) * SAH + kb + 2 * ac;
                int i1 = (mb + ar + 8) * SAH + kb + 2 * ac;
                ah[mf][0] = *(const uint32_t*)&sAh[i0];
                ah[mf][1] = *(const uint32_t*)&sAh[i1];
                ah[mf][2] = *(const uint32_t*)&sAh[i0 + 8];
                ah[mf][3] = *(const uint32_t*)&sAh[i1 + 8];
            }
            uint32_t bh[4][2];
            #pragma unroll
            for (int nf = 0; nf < 4; nf++) {
                int col = wn + nf * 8 + (lane >> 2);
                int i0 = col * SBH + kb + 2 * (lane & 3);
                bh[nf][0] = *(const uint32_t*)&sBh[i0];
                bh[nf][1] = *(const uint32_t*)&sBh[i0 + 8];
            }
            #pragma unroll
            for (int mf = 0; mf < 2; mf++)
                #pragma unroll
                for (int nf = 0; nf < 4; nf++)
                    mma_f16(acc[mf][nf], ah[mf], bh[nf]);
        }
        __syncthreads();
    }

    // ---- epilogue: store h1 (fp16) + fused attention dots ------------------
    float asv[4][2], adv[4][2];
    #pragma unroll
    for (int nf = 0; nf < 4; nf++) {
        int cb = head * HID + wn + nf * 8 + 2 * (lane & 3);
        asv[nf][0] = att_s[cb];     asv[nf][1] = att_s[cb + 1];
        adv[nf][0] = att_d[cb];     adv[nf][1] = att_d[cb + 1];
    }

    #pragma unroll
    for (int mf = 0; mf < 2; mf++) {
        int rA = row0 + wm + mf * 16 + (lane >> 2);
        int rB = rA + 8;
        float ps0 = 0.f, pd0 = 0.f, ps1 = 0.f, pd1 = 0.f;
        #pragma unroll
        for (int nf = 0; nf < 4; nf++) {
            int cb = col0 + wn + nf * 8 + 2 * (lane & 3);
            if (rA < NN)
                *(__half2*)&g_h1[(size_t)rA * C1 + cb] =
                    __floats2half2_rn(acc[mf][nf][0], acc[mf][nf][1]);
            if (rB < NN)
                *(__half2*)&g_h1[(size_t)rB * C1 + cb] =
                    __floats2half2_rn(acc[mf][nf][2], acc[mf][nf][3]);
            ps0 += acc[mf][nf][0] * asv[nf][0] + acc[mf][nf][1] * asv[nf][1];
            pd0 += acc[mf][nf][0] * adv[nf][0] + acc[mf][nf][1] * adv[nf][1];
            ps1 += acc[mf][nf][2] * asv[nf][0] + acc[mf][nf][3] * asv[nf][1];
            pd1 += acc[mf][nf][2] * adv[nf][0] + acc[mf][nf][3] * adv[nf][1];
        }
        #pragma unroll
        for (int o = 1; o <= 2; o <<= 1) {
            ps0 += __shfl_xor_sync(0xffffffffu, ps0, o);
            pd0 += __shfl_xor_sync(0xffffffffu, pd0, o);
            ps1 += __shfl_xor_sync(0xffffffffu, ps1, o);
            pd1 += __shfl_xor_sync(0xffffffffu, pd1, o);
        }
        if ((lane & 3) == 0) {
            int lr0 = wm + mf * 16 + (lane >> 2);
            parts[lr0][wnidx] = ps0;
            partd[lr0][wnidx] = pd0;
            parts[lr0 + 8][wnidx] = ps1;
            partd[lr0 + 8][wnidx] = pd1;
        }
    }
    __syncthreads();
    if (tid < 128) {
        int grow = row0 + tid;
        if (grow < NN) {
            g_as1[grow * HEADS + head] = parts[tid][0] + parts[tid][1];
            g_ad1[grow * HEADS + head] = partd[tid][0] + partd[tid][1];
        }
    }
}

// ---------------- layer-1 aggregation: 2 warps per node, unroll x4 ----------
// warp handles 256 channels (4 heads); lane owns 8 channels (one uint4 of fp16).
__device__ __forceinline__ void acc_u4(float* acc, const uint4& u, float w) {
    float2 f0 = __half22float2(*(const __half2*)&u.x);
    float2 f1 = __half22float2(*(const __half2*)&u.y);
    float2 f2 = __half22float2(*(const __half2*)&u.z);
    float2 f3 = __half22float2(*(const __half2*)&u.w);
    acc[0] += w * f0.x; acc[1] += w * f0.y;
    acc[2] += w * f1.x; acc[3] += w * f1.y;
    acc[4] += w * f2.x; acc[5] += w * f2.y;
    acc[6] += w * f3.x; acc[7] += w * f3.y;
}

__global__ void k_agg1(const float* __restrict__ b1, const float* __restrict__ W2,
                       const float* __restrict__ att_s2, const float* __restrict__ att_d2) {
    __shared__ float sW2[C1 * 2];
    __shared__ float sb1[C1];
    __shared__ float pp[4][2][2];   // [node-in-block][half][p0/p1]
    int tid = threadIdx.x;
    for (int j = tid; j < C1 * 2; j += 256) sW2[j] = W2[j];
    for (int j = tid; j < C1; j += 256) sb1[j] = b1[j];
    __syncthreads();

    int warp = tid >> 5, lane = tid & 31;
    int nidx = warp >> 1, wh = warp & 1;          // 4 nodes/block, 2 warps/node
    int node = blockIdx.x * 4 + nidx;             // NN % 4 == 0 -> always valid
    int hh = lane >> 3;                           // head slot 0..3 in this half

    int beg = g_off[node], end = g_off[node + 1];
    float adst = (lane < 4) ? g_ad1[node * HEADS + wh * 4 + lane] : 0.f;

    float s = 0.f;
    float acc[8];
    #pragma unroll
    for (int j = 0; j < 8; j++) acc[j] = 0.f;

    const __half* hbase = g_h1 + wh * 256 + lane * 8;

    int e = beg;
    for (; e + 3 < end; e += 4) {
        int s0 = g_csr[e], s1 = g_csr[e + 1], s2 = g_csr[e + 2], s3 = g_csr[e + 3];
        float w0h = 0.f, w1h = 0.f, w2h = 0.f, w3h = 0.f;
        if (lane < 4) {
            int c = wh * 4 + lane;
            float a0 = g_as1[s0 * HEADS + c] + adst;
            float a1 = g_as1[s1 * HEADS + c] + adst;
            float a2 = g_as1[s2 * HEADS + c] + adst;
            float a3 = g_as1[s3 * HEADS + c] + adst;
            a0 = a0 > 0.f ? a0 : 0.2f * a0;
            a1 = a1 > 0.f ? a1 : 0.2f * a1;
            a2 = a2 > 0.f ? a2 : 0.2f * a2;
            a3 = a3 > 0.f ? a3 : 0.2f * a3;
            w0h = __expf(a0); w1h = __expf(a1);
            w2h = __expf(a2); w3h = __expf(a3);
            s += (w0h + w1h) + (w2h + w3h);
        }
        float w0 = __shfl_sync(0xffffffffu, w0h, hh);
        float w1 = __shfl_sync(0xffffffffu, w1h, hh);
        float w2 = __shfl_sync(0xffffffffu, w2h, hh);
        float w3 = __shfl_sync(0xffffffffu, w3h, hh);
        uint4 u0 = *(const uint4*)(hbase + (size_t)s0 * C1);
        uint4 u1 = *(const uint4*)(hbase + (size_t)s1 * C1);
        uint4 u2 = *(const uint4*)(hbase + (size_t)s2 * C1);
        uint4 u3 = *(const uint4*)(hbase + (size_t)s3 * C1);
        acc_u4(acc, u0, w0);
        acc_u4(acc, u1, w1);
        acc_u4(acc, u2, w2);
        acc_u4(acc, u3, w3);
    }
    for (; e < end; e++) {
        int s0 = g_csr[e];
        float w0h = 0.f;
        if (lane < 4) {
            float a0 = g_as1[s0 * HEADS + wh * 4 + lane] + adst;
            a0 = a0 > 0.f ? a0 : 0.2f * a0;
            w0h = __expf(a0);
            s += w0h;
        }
        float w0 = __shfl_sync(0xffffffffu, w0h, hh);
        uint4 u0 = *(const uint4*)(hbase + (size_t)s0 * C1);
        acc_u4(acc, u0, w0);
    }

    float inv_h = (lane < 4) ? (1.f / s) : 0.f;
    float inv = __shfl_sync(0xffffffffu, inv_h, hh);

    // partial layer-2 dot over this half's 256 channels
    float p0 = 0.f, p1 = 0.f;
    #pragma unroll
    for (int j = 0; j < 8; j++) {
        int ch = wh * 256 + lane * 8 + j;
        float o = acc[j] * inv + sb1[ch];
        float he = o > 0.f ? o : expm1f(o);
        p0 += he * sW2[ch * 2 + 0];
        p1 += he * sW2[ch * 2 + 1];
    }
    #pragma unroll
    for (int off = 16; off >= 1; off >>= 1) {
        p0 += __shfl_xor_sync(0xffffffffu, p0, off);
        p1 += __shfl_xor_sync(0xffffffffu, p1, off);
    }
    if (lane == 0) {
        pp[nidx][wh][0] = p0;
        pp[nidx][wh][1] = p1;
    }
    __syncthreads();
    if (wh == 0 && lane == 0) {
        float q0 = pp[nidx][0][0] + pp[nidx][1][0];
        float q1 = pp[nidx][0][1] + pp[nidx][1][1];
        g_h2[node * 2 + 0] = q0;
        g_h2[node * 2 + 1] = q1;
        g_as2[node] = q0 * att_s2[0] + q1 * att_s2[1];
        g_ad2[node] = q0 * att_d2[0] + q1 * att_d2[1];
    }
}

// ---------------- layer-2 aggregation ----------------------------------------
__global__ void k_agg2(const float* __restrict__ b2, float* __restrict__ out) {
    int tid = threadIdx.x;
    int node = (blockIdx.x * 256 + tid) >> 5;
    if (node >= NN) return;
    int lane = tid & 31;

    int beg = g_off[node], end = g_off[node + 1];
    float adst = g_ad2[node];

    float s = 0.f, a0 = 0.f, a1 = 0.f;
    for (int e = beg + lane; e < end; e += 32) {
        int src = g_csr[e];
        float al = g_as2[src] + adst;
        al = al > 0.f ? al : 0.2f * al;
        float w = __expf(al);
        s  += w;
        a0 += w * g_h2[src * 2 + 0];
        a1 += w * g_h2[src * 2 + 1];
    }
    #pragma unroll
    for (int off = 16; off >= 1; off >>= 1) {
        s  += __shfl_xor_sync(0xffffffffu, s,  off);
        a0 += __shfl_xor_sync(0xffffffffu, a0, off);
        a1 += __shfl_xor_sync(0xffffffffu, a1, off);
    }
    if (lane == 0) {
        float inv = 1.f / s;
        out[node * 2 + 0] = a0 * inv + b2[0];
        out[node * 2 + 1] = a1 * inv + b2[1];
    }
}

// ---------------- launch ------------------------------------------------------
extern "C" void kernel_launch(void* const* d_in, const int* in_sizes, int n_in,
                              void* d_out, int out_size) {
    const float* x   = (const float*)d_in[0];
    const void*  ei  = d_in[1];
    const float* W1  = (const float*)d_in[2];
    const float* as1 = (const float*)d_in[3];
    const float* ad1 = (const float*)d_in[4];
    const float* b1  = (const float*)d_in[5];
    const float* W2  = (const float*)d_in[6];
    const float* as2 = (const float*)d_in[7];
    const float* ad2 = (const float*)d_in[8];
    const float* b2  = (const float*)d_in[9];
    float* out = (float*)d_out;

    k_prep<<<XB + WB + 1, 256>>>(x, W1, (const int*)ei);                   // 0
    k_count<<<(TE / 2 + 255) / 256, 256>>>(ei);                            // 1
    k_scanA<<<NBLK, 256>>>();                                              // 2
    k_gemm1<<<dim3((NN + 127) / 128, HEADS), 256>>>(as1, ad1);             // 3 <- profiled
    k_scanC<<<NBLK, 256>>>();                                              // 4
    k_scatter<<<(TE / 2 + 255) / 256, 256>>>(ei);                          // 5
    k_agg1<<<NN / 4, 256>>>(b1, W2, as2, ad2);                             // 6
    k_agg2<<<(NN * 32 + 255) / 256, 256>>>(b2, out);                       // 7
}

// round 12
// speedup vs baseline: 1.3739x; 1.0398x over previous
#include <cuda_runtime.h>
#include <cuda_fp16.h>
#include <cstdint>

#define NN 20000
#define EE 320000
#define TE (EE + NN)          // edges + self loops
#define FIN 128
#define HID 64
#define HEADS 8
#define C1 (HEADS * HID)      // 512
#define NBLK ((NN + 255) / 256)   // 79 scan blocks
#define CB ((TE / 2 + 255) / 256) // 665 count blocks
#define XB (NN * FIN / 4 / 256)   // 2500 x-convert blocks
#define WB (FIN * C1 / 256)       // 256 w-convert blocks

// ---------------- scratch (static device globals; no allocation) -------------
// g_cnt invariant: zeroed at end of every kernel_launch (agg2 tail) and
// zero-initialized at load -> always zero when k_prep's count blocks run.
__device__ int    g_is64;
__device__ int    g_cnt[NN];
__device__ int    g_off[NN + 1];
__device__ int    g_cur[NN];
__device__ int    g_csr[TE];
__device__ int    g_bsum[NBLK];
__device__ __half g_h1[(size_t)NN * C1];      // 20 MB, fp16 features
__device__ __half g_xhp[(size_t)NN * FIN];    // fp16 x            [N][128]
__device__ __half g_wth[C1 * FIN];            // fp16 W1^T         [n][k]
__device__ float  g_as1[NN * HEADS];
__device__ float  g_ad1[NN * HEADS];
__device__ float  g_h2[NN * 2];
__device__ float  g_as2[NN];
__device__ float  g_ad2[NN];

// ---------------- fused prep: edge count + x->fp16 + W1^T->fp16 --------------
__global__ void k_prep(const float* __restrict__ x, const float* __restrict__ W1,
                       const void* __restrict__ ei) {
    int b = blockIdx.x, t = threadIdx.x;
    if (b < CB) {
        // ---- count blocks (self-detecting edge dtype) ----
        __shared__ int is64_s;
        if (t < 32) {
            int hi = ((const int*)ei)[2 * t + 1];
            unsigned bl = __ballot_sync(0xffffffffu, hi == 0);
            if (t == 0) {
                is64_s = (bl == 0xffffffffu) ? 1 : 0;
                if (b == 0) g_is64 = is64_s;
            }
        }
        __syncthreads();
        int p = b * 256 + t;
        if (p >= TE / 2) return;
        int d0, d1;
        if (2 * p < EE) {
            if (is64_s) {
                longlong2 v = ((const longlong2*)ei)[EE / 2 + p];
                d0 = (int)v.x; d1 = (int)v.y;
            } else {
                int2 v = ((const int2*)ei)[EE / 2 + p];
                d0 = v.x; d1 = v.y;
            }
        } else {
            d0 = 2 * p - EE; d1 = d0 + 1;
        }
        if (d0 == d1) atomicAdd(&g_cnt[d0], 2);
        else { atomicAdd(&g_cnt[d0], 1); atomicAdd(&g_cnt[d1], 1); }
    } else if (b < CB + XB) {
        int i = (b - CB) * 256 + t;
        float4 v = ((const float4*)x)[i];
        ((__half2*)g_xhp)[2 * i + 0] = __floats2half2_rn(v.x, v.y);
        ((__half2*)g_xhp)[2 * i + 1] = __floats2half2_rn(v.z, v.w);
    } else {
        int j = (b - CB - XB) * 256 + t;
        int k = j / C1, n = j % C1;
        g_wth[n * FIN + k] = __float2half_rn(W1[j]);
    }
}

// ---------------- CSR scan ----------------------------------------------------
__global__ void k_scanA() {
    int t = threadIdx.x, b = blockIdx.x;
    int i = b * 256 + t;
    int v = (i < NN) ? g_cnt[i] : 0;
    int lane = t & 31, wid = t >> 5;
    int incl = v;
    #pragma unroll
    for (int o = 1; o < 32; o <<= 1) {
        int x = __shfl_up_sync(0xffffffffu, incl, o);
        if (lane >= o) incl += x;
    }
    __shared__ int ws[8];
    if (lane == 31) ws[wid] = incl;
    __syncthreads();
    if (t < 8) {
        int wv = ws[t];
        int wincl = wv;
        #pragma unroll
        for (int o = 1; o < 8; o <<= 1) {
            int x = __shfl_up_sync(0x000000ffu, wincl, o);
            if (t >= o) wincl += x;
        }
        ws[t] = wincl - wv;
        if (t == 7) g_bsum[b] = wincl;
    }
    __syncthreads();
    incl += ws[wid];
    if (i < NN) g_off[i + 1] = incl;
}

__global__ void k_scanC() {
    __shared__ int carry_s;
    int t = threadIdx.x, b = blockIdx.x;
    if (t < 32) {
        int c = 0;
        for (int i = t; i < b; i += 32) c += g_bsum[i];
        #pragma unroll
        for (int o = 16; o >= 1; o >>= 1) c += __shfl_xor_sync(0xffffffffu, c, o);
        if (t == 0) carry_s = c;
    }
    __syncthreads();
    if (b == 0 && t == 0) g_off[0] = 0;
    int i = b * 256 + t;
    if (i >= NN) return;
    int off = carry_s + g_off[i + 1];
    g_off[i + 1] = off;
    g_cur[i] = off - g_cnt[i];
}

__global__ void k_scatter(const void* ei) {
    int p = blockIdx.x * blockDim.x + threadIdx.x;
    if (p >= TE / 2) return;
    int s0, s1, d0, d1;
    if (2 * p < EE) {
        if (g_is64) {
            longlong2 sv = ((const longlong2*)ei)[p];
            longlong2 dv = ((const longlong2*)ei)[EE / 2 + p];
            s0 = (int)sv.x; s1 = (int)sv.y;
            d0 = (int)dv.x; d1 = (int)dv.y;
        } else {
            int2 sv = ((const int2*)ei)[p];
            int2 dv = ((const int2*)ei)[EE / 2 + p];
            s0 = sv.x; s1 = sv.y;
            d0 = dv.x; d1 = dv.y;
        }
    } else {
        s0 = d0 = 2 * p - EE;
        s1 = d1 = s0 + 1;
    }
    if (d0 == d1) {
        int pos = atomicAdd(&g_cur[d0], 2);
        g_csr[pos] = s0;
        g_csr[pos + 1] = s1;
    } else {
        g_csr[atomicAdd(&g_cur[d0], 1)] = s0;
        g_csr[atomicAdd(&g_cur[d1], 1)] = s1;
    }
}

// ---------------- fp16 mma -----------------------------------------------------
__device__ __forceinline__ void mma_f16(float c[4], const uint32_t a[4], const uint32_t b[2]) {
    asm("mma.sync.aligned.m16n8k16.row.col.f32.f16.f16.f32 "
        "{%0,%1,%2,%3},{%4,%5,%6,%7},{%8,%9},{%0,%1,%2,%3};"
        : "+f"(c[0]), "+f"(c[1]), "+f"(c[2]), "+f"(c[3])
        : "r"(a[0]), "r"(a[1]), "r"(a[2]), "r"(a[3]), "r"(b[0]), "r"(b[1]));
}

// ---------------- GEMM1: h1 = fp16(x) @ fp16(W1), fused att epilogue ---------
// grid (157, 8) ; block 256 = 8 warps (4 m x 2 n); BM=128 BN=64 BK=32
#define SAH 40
#define SBH 40
__global__ void __launch_bounds__(256, 3)
k_gemm1(const float* __restrict__ att_s, const float* __restrict__ att_d) {
    __shared__ __align__(16) __half sAh[128 * SAH];   // 10.0 KB
    __shared__ __align__(16) __half sBh[64 * SBH];    // 5.0 KB
    __shared__ float parts[128][2];
    __shared__ float partd[128][2];

    int tid = threadIdx.x;
    int warp = tid >> 5, lane = tid & 31;
    int wm = (warp >> 1) * 32;
    int wnidx = warp & 1;
    int wn = wnidx * 32;
    int row0 = blockIdx.x * 128;
    int head = blockIdx.y;
    int col0 = head * 64;

    float acc[2][4][4];
    #pragma unroll
    for (int i = 0; i < 2; i++)
        #pragma unroll
        for (int j = 0; j < 4; j++)
            #pragma unroll
            for (int q = 0; q < 4; q++) acc[i][j][q] = 0.f;

    int ar = lane >> 2, ac = lane & 3;

    for (int chunk = 0; chunk < 4; chunk++) {
        int kk = chunk * 32;
        #pragma unroll
        for (int r = 0; r < 2; r++) {
            int idx = tid + 256 * r;
            int m = idx >> 2, q = idx & 3;
            int grow = row0 + m;
            uint4 vh = make_uint4(0u, 0u, 0u, 0u);
            if (grow < NN)
                vh = *(const uint4*)&g_xhp[(size_t)grow * FIN + kk + q * 8];
            *(uint4*)&sAh[m * SAH + q * 8] = vh;
        }
        {
            int n = tid >> 2, q = tid & 3;
            size_t g = (size_t)(col0 + n) * FIN + kk + q * 8;
            *(uint4*)&sBh[n * SBH + q * 8] = *(const uint4*)&g_wth[g];
        }
        __syncthreads();

        #pragma unroll
        for (int ks = 0; ks < 2; ks++) {
            int kb = ks * 16;
            uint32_t ah[2][4];
            #pragma unroll
            for (int mf = 0; mf < 2; mf++) {
                int mb = wm + mf * 16;
                int i0 = (mb + ar) * SAH + kb + 2 * ac;
                int i1 = (mb + ar + 8) * SAH + kb + 2 * ac;
                ah[mf][0] = *(const uint32_t*)&sAh[i0];
                ah[mf][1] = *(const uint32_t*)&sAh[i1];
                ah[mf][2] = *(const uint32_t*)&sAh[i0 + 8];
                ah[mf][3] = *(const uint32_t*)&sAh[i1 + 8];
            }
            uint32_t bh[4][2];
            #pragma unroll
            for (int nf = 0; nf < 4; nf++) {
                int col = wn + nf * 8 + (lane >> 2);
                int i0 = col * SBH + kb + 2 * (lane & 3);
                bh[nf][0] = *(const uint32_t*)&sBh[i0];
                bh[nf][1] = *(const uint32_t*)&sBh[i0 + 8];
            }
            #pragma unroll
            for (int mf = 0; mf < 2; mf++)
                #pragma unroll
                for (int nf = 0; nf < 4; nf++)
                    mma_f16(acc[mf][nf], ah[mf], bh[nf]);
        }
        __syncthreads();
    }

    // ---- epilogue: store h1 (fp16) + fused attention dots ------------------
    float asv[4][2], adv[4][2];
    #pragma unroll
    for (int nf = 0; nf < 4; nf++) {
        int cb = head * HID + wn + nf * 8 + 2 * (lane & 3);
        asv[nf][0] = att_s[cb];     asv[nf][1] = att_s[cb + 1];
        adv[nf][0] = att_d[cb];     adv[nf][1] = att_d[cb + 1];
    }

    #pragma unroll
    for (int mf = 0; mf < 2; mf++) {
        int rA = row0 + wm + mf * 16 + (lane >> 2);
        int rB = rA + 8;
        float ps0 = 0.f, pd0 = 0.f, ps1 = 0.f, pd1 = 0.f;
        #pragma unroll
        for (int nf = 0; nf < 4; nf++) {
            int cb = col0 + wn + nf * 8 + 2 * (lane & 3);
            if (rA < NN)
                *(__half2*)&g_h1[(size_t)rA * C1 + cb] =
                    __floats2half2_rn(acc[mf][nf][0], acc[mf][nf][1]);
            if (rB < NN)
                *(__half2*)&g_h1[(size_t)rB * C1 + cb] =
                    __floats2half2_rn(acc[mf][nf][2], acc[mf][nf][3]);
            ps0 += acc[mf][nf][0] * asv[nf][0] + acc[mf][nf][1] * asv[nf][1];
            pd0 += acc[mf][nf][0] * adv[nf][0] + acc[mf][nf][1] * adv[nf][1];
            ps1 += acc[mf][nf][2] * asv[nf][0] + acc[mf][nf][3] * asv[nf][1];
            pd1 += acc[mf][nf][2] * adv[nf][0] + acc[mf][nf][3] * adv[nf][1];
        }
        #pragma unroll
        for (int o = 1; o <= 2; o <<= 1) {
            ps0 += __shfl_xor_sync(0xffffffffu, ps0, o);
            pd0 += __shfl_xor_sync(0xffffffffu, pd0, o);
            ps1 += __shfl_xor_sync(0xffffffffu, ps1, o);
            pd1 += __shfl_xor_sync(0xffffffffu, pd1, o);
        }
        if ((lane & 3) == 0) {
            int lr0 = wm + mf * 16 + (lane >> 2);
            parts[lr0][wnidx] = ps0;
            partd[lr0][wnidx] = pd0;
            parts[lr0 + 8][wnidx] = ps1;
            partd[lr0 + 8][wnidx] = pd1;
        }
    }
    __syncthreads();
    if (tid < 128) {
        int grow = row0 + tid;
        if (grow < NN) {
            g_as1[grow * HEADS + head] = parts[tid][0] + parts[tid][1];
            g_ad1[grow * HEADS + head] = partd[tid][0] + partd[tid][1];
        }
    }
}

// ---------------- layer-1 aggregation: 2 warps/node, 8-edge groups ----------
// Per group: lane (j=lane>>2, h=lane&3) computes ONE logit exp for (edge j,
// head h of this warp's half); per-head sums recovered via xor-shuffles.
// Feature gathers use uniform csr loads: 8 independent LDG.128 per warp.
__device__ __forceinline__ void acc_u4(float* acc, const uint4& u, float w) {
    float2 f0 = __half22float2(*(const __half2*)&u.x);
    float2 f1 = __half22float2(*(const __half2*)&u.y);
    float2 f2 = __half22float2(*(const __half2*)&u.z);
    float2 f3 = __half22float2(*(const __half2*)&u.w);
    acc[0] += w * f0.x; acc[1] += w * f0.y;
    acc[2] += w * f1.x; acc[3] += w * f1.y;
    acc[4] += w * f2.x; acc[5] += w * f2.y;
    acc[6] += w * f3.x; acc[7] += w * f3.y;
}

__global__ void k_agg1(const float* __restrict__ b1, const float* __restrict__ W2,
                       const float* __restrict__ att_s2, const float* __restrict__ att_d2) {
    __shared__ float sW2[C1 * 2];
    __shared__ float sb1[C1];
    __shared__ float pp[4][2][2];   // [node-in-block][half][p0/p1]
    int tid = threadIdx.x;
    for (int j = tid; j < C1 * 2; j += 256) sW2[j] = W2[j];
    for (int j = tid; j < C1; j += 256) sb1[j] = b1[j];
    __syncthreads();

    int warp = tid >> 5, lane = tid & 31;
    int nidx = warp >> 1, wh = warp & 1;          // 4 nodes/block, 2 warps/node
    int node = blockIdx.x * 4 + nidx;             // NN % 4 == 0 -> always valid
    int hh = lane >> 3;                           // owned-channel head slot 0..3
    int jj = lane >> 2, h4 = lane & 3;            // logit work assignment

    int beg = g_off[node], end = g_off[node + 1];
    float adst_r = (lane < 4) ? g_ad1[node * HEADS + wh * 4 + lane] : 0.f;
    float adh = __shfl_sync(0xffffffffu, adst_r, h4);   // adst for head h4

    float s = 0.f;
    float acc[8];
    #pragma unroll
    for (int j = 0; j < 8; j++) acc[j] = 0.f;

    const __half* hbase = g_h1 + wh * 256 + lane * 8;

    for (int e = beg; e < end; e += 8) {
        int m = end - e; if (m > 8) m = 8;
        float w = 0.f;
        if (jj < m) {
            int sj = g_csr[e + jj];
            float a = g_as1[sj * HEADS + wh * 4 + h4] + adh;
            a = a > 0.f ? a : 0.2f * a;
            w = __expf(a);
            s += w;
        }
        #pragma unroll
        for (int q = 0; q < 8; q++) {
            if (q < m) {
                int srcq = g_csr[e + q];     // uniform broadcast load
                float wq = __shfl_sync(0xffffffffu, w, 4 * q + hh);
                uint4 u = *(const uint4*)(hbase + (size_t)srcq * C1);
                acc_u4(acc, u, wq);
            }
        }
    }

    // per-head softmax sums: combine lanes differing in bits 2..4
    s += __shfl_xor_sync(0xffffffffu, s, 4);
    s += __shfl_xor_sync(0xffffffffu, s, 8);
    s += __shfl_xor_sync(0xffffffffu, s, 16);
    float inv = 1.f / __shfl_sync(0xffffffffu, s, hh);

    // partial layer-2 dot over this half's 256 channels
    float p0 = 0.f, p1 = 0.f;
    #pragma unroll
    for (int j = 0; j < 8; j++) {
        int ch = wh * 256 + lane * 8 + j;
        float o = acc[j] * inv + sb1[ch];
        float he = o > 0.f ? o : expm1f(o);
        p0 += he * sW2[ch * 2 + 0];
        p1 += he * sW2[ch * 2 + 1];
    }
    #pragma unroll
    for (int off = 16; off >= 1; off >>= 1) {
        p0 += __shfl_xor_sync(0xffffffffu, p0, off);
        p1 += __shfl_xor_sync(0xffffffffu, p1, off);
    }
    if (lane == 0) {
        pp[nidx][wh][0] = p0;
        pp[nidx][wh][1] = p1;
    }
    __syncthreads();
    if (wh == 0 && lane == 0) {
        float q0 = pp[nidx][0][0] + pp[nidx][1][0];
        float q1 = pp[nidx][0][1] + pp[nidx][1][1];
        g_h2[node * 2 + 0] = q0;
        g_h2[node * 2 + 1] = q1;
        g_as2[node] = q0 * att_s2[0] + q1 * att_s2[1];
        g_ad2[node] = q0 * att_d2[0] + q1 * att_d2[1];
    }
}

// ---------------- layer-2 aggregation (+ g_cnt re-zero for next call) --------
__global__ void k_agg2(const float* __restrict__ b2, float* __restrict__ out) {
    int tid = threadIdx.x;
    int gi = blockIdx.x * 256 + tid;
    if (gi < NN) g_cnt[gi] = 0;        // restore invariant for next launch
    int node = gi >> 5;
    if (node >= NN) return;
    int lane = tid & 31;

    int beg = g_off[node], end = g_off[node + 1];
    float adst = g_ad2[node];

    float s = 0.f, a0 = 0.f, a1 = 0.f;
    for (int e = beg + lane; e < end; e += 32) {
        int src = g_csr[e];
        float al = g_as2[src] + adst;
        al = al > 0.f ? al : 0.2f * al;
        float w = __expf(al);
        s  += w;
        a0 += w * g_h2[src * 2 + 0];
        a1 += w * g_h2[src * 2 + 1];
    }
    #pragma unroll
    for (int off = 16; off >= 1; off >>= 1) {
        s  += __shfl_xor_sync(0xffffffffu, s,  off);
        a0 += __shfl_xor_sync(0xffffffffu, a0, off);
        a1 += __shfl_xor_sync(0xffffffffu, a1, off);
    }
    if (lane == 0) {
        float inv = 1.f / s;
        out[node * 2 + 0] = a0 * inv + b2[0];
        out[node * 2 + 1] = a1 * inv + b2[1];
    }
}

// ---------------- launch ------------------------------------------------------
extern "C" void kernel_launch(void* const* d_in, const int* in_sizes, int n_in,
                              void* d_out, int out_size) {
    const float* x   = (const float*)d_in[0];
    const void*  ei  = d_in[1];
    const float* W1  = (const float*)d_in[2];
    const float* as1 = (const float*)d_in[3];
    const float* ad1 = (const float*)d_in[4];
    const float* b1  = (const float*)d_in[5];
    const float* W2  = (const float*)d_in[6];
    const float* as2 = (const float*)d_in[7];
    const float* ad2 = (const float*)d_in[8];
    const float* b2  = (const float*)d_in[9];
    float* out = (float*)d_out;

    k_prep<<<CB + XB + WB, 256>>>(x, W1, ei);                              // 0
    k_scanA<<<NBLK, 256>>>();                                              // 1
    k_scanC<<<NBLK, 256>>>();                                              // 2
    k_gemm1<<<dim3((NN + 127) / 128, HEADS), 256>>>(as1, ad1);             // 3 <- profiled
    k_scatter<<<(TE / 2 + 255) / 256, 256>>>(ei);                          // 4
    k_agg1<<<NN / 4, 256>>>(b1, W2, as2, ad2);                             // 5
    k_agg2<<<(NN * 32 + 255) / 256, 256>>>(b2, out);                       // 6
}

// round 13
// speedup vs baseline: 1.4271x; 1.0388x over previous
#include <cuda_runtime.h>
#include <cuda_fp16.h>
#include <cstdint>

#define NN 20000
#define EE 320000
#define TE (EE + NN)          // edges + self loops
#define FIN 128
#define HID 64
#define HEADS 8
#define C1 (HEADS * HID)      // 512
#define NBLK ((NN + 255) / 256)   // 79 scan blocks
#define CB ((TE / 2 + 255) / 256) // 665 count/scatter blocks
#define XB (NN * FIN / 4 / 256)   // 2500 x-convert blocks
#define WB (FIN * C1 / 256)       // 256 w-convert blocks

// ---------------- scratch (static device globals; no allocation) -------------
// g_cnt invariant: zeroed at end of every kernel_launch (agg2 tail) and
// zero-initialized at load -> always zero when k_count runs.
__device__ int    g_is64;
__device__ int    g_cnt[NN];
__device__ int    g_off[NN + 1];
__device__ int    g_cur[NN];
__device__ int    g_csr[TE];
__device__ int    g_bsum[NBLK];
__device__ __half g_h1[(size_t)NN * C1];      // 20 MB, fp16 features
__device__ __half g_xhp[(size_t)NN * FIN];    // fp16 x            [N][128]
__device__ __half g_wth[C1 * FIN];            // fp16 W1^T         [n][k]
__device__ float  g_as1[NN * HEADS];
__device__ float  g_ad1[NN * HEADS];
__device__ float  g_h2[NN * 2];
__device__ float  g_as2[NN];
__device__ float  g_ad2[NN];

// ---------------- conversions: x->fp16 + W1^T->fp16 (main stream) ------------
__global__ void k_conv(const float* __restrict__ x, const float* __restrict__ W1) {
    int b = blockIdx.x, t = threadIdx.x;
    if (b < XB) {
        int i = b * 256 + t;
        float4 v = ((const float4*)x)[i];
        ((__half2*)g_xhp)[2 * i + 0] = __floats2half2_rn(v.x, v.y);
        ((__half2*)g_xhp)[2 * i + 1] = __floats2half2_rn(v.z, v.w);
    } else {
        int j = (b - XB) * 256 + t;
        int k = j / C1, n = j % C1;
        g_wth[n * FIN + k] = __float2half_rn(W1[j]);
    }
}

// ---------------- CSR build (side stream) -------------------------------------
__global__ void k_count(const void* __restrict__ ei) {
    __shared__ int is64_s;
    int b = blockIdx.x, t = threadIdx.x;
    if (t < 32) {
        int hi = ((const int*)ei)[2 * t + 1];
        unsigned bl = __ballot_sync(0xffffffffu, hi == 0);
        if (t == 0) {
            is64_s = (bl == 0xffffffffu) ? 1 : 0;
            if (b == 0) g_is64 = is64_s;
        }
    }
    __syncthreads();
    int p = b * 256 + t;
    if (p >= TE / 2) return;
    int d0, d1;
    if (2 * p < EE) {
        if (is64_s) {
            longlong2 v = ((const longlong2*)ei)[EE / 2 + p];
            d0 = (int)v.x; d1 = (int)v.y;
        } else {
            int2 v = ((const int2*)ei)[EE / 2 + p];
            d0 = v.x; d1 = v.y;
        }
    } else {
        d0 = 2 * p - EE; d1 = d0 + 1;
    }
    if (d0 == d1) atomicAdd(&g_cnt[d0], 2);
    else { atomicAdd(&g_cnt[d0], 1); atomicAdd(&g_cnt[d1], 1); }
}

__global__ void k_scanA() {
    int t = threadIdx.x, b = blockIdx.x;
    int i = b * 256 + t;
    int v = (i < NN) ? g_cnt[i] : 0;
    int lane = t & 31, wid = t >> 5;
    int incl = v;
    #pragma unroll
    for (int o = 1; o < 32; o <<= 1) {
        int x = __shfl_up_sync(0xffffffffu, incl, o);
        if (lane >= o) incl += x;
    }
    __shared__ int ws[8];
    if (lane == 31) ws[wid] = incl;
    __syncthreads();
    if (t < 8) {
        int wv = ws[t];
        int wincl = wv;
        #pragma unroll
        for (int o = 1; o < 8; o <<= 1) {
            int x = __shfl_up_sync(0x000000ffu, wincl, o);
            if (t >= o) wincl += x;
        }
        ws[t] = wincl - wv;
        if (t == 7) g_bsum[b] = wincl;
    }
    __syncthreads();
    incl += ws[wid];
    if (i < NN) g_off[i + 1] = incl;
}

__global__ void k_scanC() {
    __shared__ int carry_s;
    int t = threadIdx.x, b = blockIdx.x;
    if (t < 32) {
        int c = 0;
        for (int i = t; i < b; i += 32) c += g_bsum[i];
        #pragma unroll
        for (int o = 16; o >= 1; o >>= 1) c += __shfl_xor_sync(0xffffffffu, c, o);
        if (t == 0) carry_s = c;
    }
    __syncthreads();
    if (b == 0 && t == 0) g_off[0] = 0;
    int i = b * 256 + t;
    if (i >= NN) return;
    int off = carry_s + g_off[i + 1];
    g_off[i + 1] = off;
    g_cur[i] = off - g_cnt[i];
}

__global__ void k_scatter(const void* __restrict__ ei) {
    int p = blockIdx.x * blockDim.x + threadIdx.x;
    if (p >= TE / 2) return;
    int s0, s1, d0, d1;
    if (2 * p < EE) {
        if (g_is64) {
            longlong2 sv = ((const longlong2*)ei)[p];
            longlong2 dv = ((const longlong2*)ei)[EE / 2 + p];
            s0 = (int)sv.x; s1 = (int)sv.y;
            d0 = (int)dv.x; d1 = (int)dv.y;
        } else {
            int2 sv = ((const int2*)ei)[p];
            int2 dv = ((const int2*)ei)[EE / 2 + p];
            s0 = sv.x; s1 = sv.y;
            d0 = dv.x; d1 = dv.y;
        }
    } else {
        s0 = d0 = 2 * p - EE;
        s1 = d1 = s0 + 1;
    }
    if (d0 == d1) {
        int pos = atomicAdd(&g_cur[d0], 2);
        g_csr[pos] = s0;
        g_csr[pos + 1] = s1;
    } else {
        g_csr[atomicAdd(&g_cur[d0], 1)] = s0;
        g_csr[atomicAdd(&g_cur[d1], 1)] = s1;
    }
}

// ---------------- fp16 mma -----------------------------------------------------
__device__ __forceinline__ void mma_f16(float c[4], const uint32_t a[4], const uint32_t b[2]) {
    asm("mma.sync.aligned.m16n8k16.row.col.f32.f16.f16.f32 "
        "{%0,%1,%2,%3},{%4,%5,%6,%7},{%8,%9},{%0,%1,%2,%3};"
        : "+f"(c[0]), "+f"(c[1]), "+f"(c[2]), "+f"(c[3])
        : "r"(a[0]), "r"(a[1]), "r"(a[2]), "r"(a[3]), "r"(b[0]), "r"(b[1]));
}

// ---------------- GEMM1: h1 = fp16(x) @ fp16(W1), fused att epilogue ---------
#define SAH 40
#define SBH 40
__global__ void __launch_bounds__(256, 3)
k_gemm1(const float* __restrict__ att_s, const float* __restrict__ att_d) {
    __shared__ __align__(16) __half sAh[128 * SAH];   // 10.0 KB
    __shared__ __align__(16) __half sBh[64 * SBH];    // 5.0 KB
    __shared__ float parts[128][2];
    __shared__ float partd[128][2];

    int tid = threadIdx.x;
    int warp = tid >> 5, lane = tid & 31;
    int wm = (warp >> 1) * 32;
    int wnidx = warp & 1;
    int wn = wnidx * 32;
    int row0 = blockIdx.x * 128;
    int head = blockIdx.y;
    int col0 = head * 64;

    float acc[2][4][4];
    #pragma unroll
    for (int i = 0; i < 2; i++)
        #pragma unroll
        for (int j = 0; j < 4; j++)
            #pragma unroll
            for (int q = 0; q < 4; q++) acc[i][j][q] = 0.f;

    int ar = lane >> 2, ac = lane & 3;

    for (int chunk = 0; chunk < 4; chunk++) {
        int kk = chunk * 32;
        #pragma unroll
        for (int r = 0; r < 2; r++) {
            int idx = tid + 256 * r;
            int m = idx >> 2, q = idx & 3;
            int grow = row0 + m;
            uint4 vh = make_uint4(0u, 0u, 0u, 0u);
            if (grow < NN)
                vh = *(const uint4*)&g_xhp[(size_t)grow * FIN + kk + q * 8];
            *(uint4*)&sAh[m * SAH + q * 8] = vh;
        }
        {
            int n = tid >> 2, q = tid & 3;
            size_t g = (size_t)(col0 + n) * FIN + kk + q * 8;
            *(uint4*)&sBh[n * SBH + q * 8] = *(const uint4*)&g_wth[g];
        }
        __syncthreads();

        #pragma unroll
        for (int ks = 0; ks < 2; ks++) {
            int kb = ks * 16;
            uint32_t ah[2][4];
            #pragma unroll
            for (int mf = 0; mf < 2; mf++) {
                int mb = wm + mf * 16;
                int i0 = (mb + ar) * SAH + kb + 2 * ac;
                int i1 = (mb + ar + 8) * SAH + kb + 2 * ac;
                ah[mf][0] = *(const uint32_t*)&sAh[i0];
                ah[mf][1] = *(const uint32_t*)&sAh[i1];
                ah[mf][2] = *(const uint32_t*)&sAh[i0 + 8];
                ah[mf][3] = *(const uint32_t*)&sAh[i1 + 8];
            }
            uint32_t bh[4][2];
            #pragma unroll
            for (int nf = 0; nf < 4; nf++) {
                int col = wn + nf * 8 + (lane >> 2);
                int i0 = col * SBH + kb + 2 * (lane & 3);
                bh[nf][0] = *(const uint32_t*)&sBh[i0];
                bh[nf][1] = *(const uint32_t*)&sBh[i0 + 8];
            }
            #pragma unroll
            for (int mf = 0; mf < 2; mf++)
                #pragma unroll
                for (int nf = 0; nf < 4; nf++)
                    mma_f16(acc[mf][nf], ah[mf], bh[nf]);
        }
        __syncthreads();
    }

    float asv[4][2], adv[4][2];
    #pragma unroll
    for (int nf = 0; nf < 4; nf++) {
        int cb = head * HID + wn + nf * 8 + 2 * (lane & 3);
        asv[nf][0] = att_s[cb];     asv[nf][1] = att_s[cb + 1];
        adv[nf][0] = att_d[cb];     adv[nf][1] = att_d[cb + 1];
    }

    #pragma unroll
    for (int mf = 0; mf < 2; mf++) {
        int rA = row0 + wm + mf * 16 + (lane >> 2);
        int rB = rA + 8;
        float ps0 = 0.f, pd0 = 0.f, ps1 = 0.f, pd1 = 0.f;
        #pragma unroll
        for (int nf = 0; nf < 4; nf++) {
            int cb = col0 + wn + nf * 8 + 2 * (lane & 3);
            if (rA < NN)
                *(__half2*)&g_h1[(size_t)rA * C1 + cb] =
                    __floats2half2_rn(acc[mf][nf][0], acc[mf][nf][1]);
            if (rB < NN)
                *(__half2*)&g_h1[(size_t)rB * C1 + cb] =
                    __floats2half2_rn(acc[mf][nf][2], acc[mf][nf][3]);
            ps0 += acc[mf][nf][0] * asv[nf][0] + acc[mf][nf][1] * asv[nf][1];
            pd0 += acc[mf][nf][0] * adv[nf][0] + acc[mf][nf][1] * adv[nf][1];
            ps1 += acc[mf][nf][2] * asv[nf][0] + acc[mf][nf][3] * asv[nf][1];
            pd1 += acc[mf][nf][2] * adv[nf][0] + acc[mf][nf][3] * adv[nf][1];
        }
        #pragma unroll
        for (int o = 1; o <= 2; o <<= 1) {
            ps0 += __shfl_xor_sync(0xffffffffu, ps0, o);
            pd0 += __shfl_xor_sync(0xffffffffu, pd0, o);
            ps1 += __shfl_xor_sync(0xffffffffu, ps1, o);
            pd1 += __shfl_xor_sync(0xffffffffu, pd1, o);
        }
        if ((lane & 3) == 0) {
            int lr0 = wm + mf * 16 + (lane >> 2);
            parts[lr0][wnidx] = ps0;
            partd[lr0][wnidx] = pd0;
            parts[lr0 + 8][wnidx] = ps1;
            partd[lr0 + 8][wnidx] = pd1;
        }
    }
    __syncthreads();
    if (tid < 128) {
        int grow = row0 + tid;
        if (grow < NN) {
            g_as1[grow * HEADS + head] = parts[tid][0] + parts[tid][1];
            g_ad1[grow * HEADS + head] = partd[tid][0] + partd[tid][1];
        }
    }
}

// ---------------- layer-1 aggregation: 2 warps/node, 8-edge groups ----------
__device__ __forceinline__ void acc_u4(float* acc, const uint4& u, float w) {
    float2 f0 = __half22float2(*(const __half2*)&u.x);
    float2 f1 = __half22float2(*(const __half2*)&u.y);
    float2 f2 = __half22float2(*(const __half2*)&u.z);
    float2 f3 = __half22float2(*(const __half2*)&u.w);
    acc[0] += w * f0.x; acc[1] += w * f0.y;
    acc[2] += w * f1.x; acc[3] += w * f1.y;
    acc[4] += w * f2.x; acc[5] += w * f2.y;
    acc[6] += w * f3.x; acc[7] += w * f3.y;
}

__global__ void k_agg1(const float* __restrict__ b1, const float* __restrict__ W2,
                       const float* __restrict__ att_s2, const float* __restrict__ att_d2) {
    __shared__ float sW2[C1 * 2];
    __shared__ float sb1[C1];
    __shared__ float pp[4][2][2];
    int tid = threadIdx.x;
    for (int j = tid; j < C1 * 2; j += 256) sW2[j] = W2[j];
    for (int j = tid; j < C1; j += 256) sb1[j] = b1[j];
    __syncthreads();

    int warp = tid >> 5, lane = tid & 31;
    int nidx = warp >> 1, wh = warp & 1;
    int node = blockIdx.x * 4 + nidx;
    int hh = lane >> 3;
    int jj = lane >> 2, h4 = lane & 3;

    int beg = g_off[node], end = g_off[node + 1];
    float adst_r = (lane < 4) ? g_ad1[node * HEADS + wh * 4 + lane] : 0.f;
    float adh = __shfl_sync(0xffffffffu, adst_r, h4);

    float s = 0.f;
    float acc[8];
    #pragma unroll
    for (int j = 0; j < 8; j++) acc[j] = 0.f;

    const __half* hbase = g_h1 + wh * 256 + lane * 8;

    for (int e = beg; e < end; e += 8) {
        int m = end - e; if (m > 8) m = 8;
        float w = 0.f;
        if (jj < m) {
            int sj = g_csr[e + jj];
            float a = g_as1[sj * HEADS + wh * 4 + h4] + adh;
            a = a > 0.f ? a : 0.2f * a;
            w = __expf(a);
            s += w;
        }
        #pragma unroll
        for (int q = 0; q < 8; q++) {
            if (q < m) {
                int srcq = g_csr[e + q];
                float wq = __shfl_sync(0xffffffffu, w, 4 * q + hh);
                uint4 u = *(const uint4*)(hbase + (size_t)srcq * C1);
                acc_u4(acc, u, wq);
            }
        }
    }

    s += __shfl_xor_sync(0xffffffffu, s, 4);
    s += __shfl_xor_sync(0xffffffffu, s, 8);
    s += __shfl_xor_sync(0xffffffffu, s, 16);
    float inv = 1.f / __shfl_sync(0xffffffffu, s, hh);

    float p0 = 0.f, p1 = 0.f;
    #pragma unroll
    for (int j = 0; j < 8; j++) {
        int ch = wh * 256 + lane * 8 + j;
        float o = acc[j] * inv + sb1[ch];
        float he = o > 0.f ? o : expm1f(o);
        p0 += he * sW2[ch * 2 + 0];
        p1 += he * sW2[ch * 2 + 1];
    }
    #pragma unroll
    for (int off = 16; off >= 1; off >>= 1) {
        p0 += __shfl_xor_sync(0xffffffffu, p0, off);
        p1 += __shfl_xor_sync(0xffffffffu, p1, off);
    }
    if (lane == 0) {
        pp[nidx][wh][0] = p0;
        pp[nidx][wh][1] = p1;
    }
    __syncthreads();
    if (wh == 0 && lane == 0) {
        float q0 = pp[nidx][0][0] + pp[nidx][1][0];
        float q1 = pp[nidx][0][1] + pp[nidx][1][1];
        g_h2[node * 2 + 0] = q0;
        g_h2[node * 2 + 1] = q1;
        g_as2[node] = q0 * att_s2[0] + q1 * att_s2[1];
        g_ad2[node] = q0 * att_d2[0] + q1 * att_d2[1];
    }
}

// ---------------- layer-2 aggregation (+ g_cnt re-zero for next call) --------
__global__ void k_agg2(const float* __restrict__ b2, float* __restrict__ out) {
    int tid = threadIdx.x;
    int gi = blockIdx.x * 256 + tid;
    if (gi < NN) g_cnt[gi] = 0;
    int node = gi >> 5;
    if (node >= NN) return;
    int lane = tid & 31;

    int beg = g_off[node], end = g_off[node + 1];
    float adst = g_ad2[node];

    float s = 0.f, a0 = 0.f, a1 = 0.f;
    for (int e = beg + lane; e < end; e += 32) {
        int src = g_csr[e];
        float al = g_as2[src] + adst;
        al = al > 0.f ? al : 0.2f * al;
        float w = __expf(al);
        s  += w;
        a0 += w * g_h2[src * 2 + 0];
        a1 += w * g_h2[src * 2 + 1];
    }
    #pragma unroll
    for (int off = 16; off >= 1; off >>= 1) {
        s  += __shfl_xor_sync(0xffffffffu, s,  off);
        a0 += __shfl_xor_sync(0xffffffffu, a0, off);
        a1 += __shfl_xor_sync(0xffffffffu, a1, off);
    }
    if (lane == 0) {
        float inv = 1.f / s;
        out[node * 2 + 0] = a0 * inv + b2[0];
        out[node * 2 + 1] = a1 * inv + b2[1];
    }
}

// ---------------- launch: two-stream overlap inside graph capture -------------
static cudaStream_t g_s2 = nullptr;
static cudaEvent_t  g_evf = nullptr, g_evj = nullptr;

extern "C" void kernel_launch(void* const* d_in, const int* in_sizes, int n_in,
                              void* d_out, int out_size) {
    const float* x   = (const float*)d_in[0];
    const void*  ei  = d_in[1];
    const float* W1  = (const float*)d_in[2];
    const float* as1 = (const float*)d_in[3];
    const float* ad1 = (const float*)d_in[4];
    const float* b1  = (const float*)d_in[5];
    const float* W2  = (const float*)d_in[6];
    const float* as2 = (const float*)d_in[7];
    const float* ad2 = (const float*)d_in[8];
    const float* b2  = (const float*)d_in[9];
    float* out = (float*)d_out;

    if (g_s2 == nullptr) {   // first call is the uncaptured correctness run
        cudaStreamCreateWithFlags(&g_s2, cudaStreamNonBlocking);
        cudaEventCreateWithFlags(&g_evf, cudaEventDisableTiming);
        cudaEventCreateWithFlags(&g_evj, cudaEventDisableTiming);
    }

    // fork: side stream builds CSR while main stream converts + runs GEMM1
    cudaEventRecord(g_evf, 0);
    cudaStreamWaitEvent(g_s2, g_evf, 0);

    k_count<<<CB, 256, 0, g_s2>>>(ei);
    k_scanA<<<NBLK, 256, 0, g_s2>>>();
    k_scanC<<<NBLK, 256, 0, g_s2>>>();
    k_scatter<<<CB, 256, 0, g_s2>>>(ei);
    cudaEventRecord(g_evj, g_s2);

    k_conv<<<XB + WB, 256>>>(x, W1);
    k_gemm1<<<dim3((NN + 127) / 128, HEADS), 256>>>(as1, ad1);

    // join: aggregation needs both CSR and h1
    cudaStreamWaitEvent(0, g_evj, 0);
    k_agg1<<<NN / 4, 256>>>(b1, W2, as2, ad2);
    k_agg2<<<(NN * 32 + 255) / 256, 256>>>(b2, out);
}